// round 12
// baseline (speedup 1.0000x reference)
#include <cuda_runtime.h>
#include <cuda_fp16.h>
#include <math.h>
#include <stdint.h>

#define S_LEN  1024
#define BATCH  4
#define HEADS  16
#define DKV    64
#define DMODEL 1024
#define BHD    (BATCH * HEADS)

// ---------------- scratch (device globals; no allocation allowed) ----------------
__device__ half g_hsH[4096 * 1024];
__device__ half g_hsL[4096 * 1024];
__device__ half g_WH[4 * 1024 * 1024];        // q,k,v,o
__device__ half g_WL[4 * 1024 * 1024];
__device__ half g_QKVH[3 * BHD * 1024 * 64];  // z: 0 Q, 1 K, 2 V; [bh][s][64]
__device__ half g_QKVL[3 * BHD * 1024 * 64];  // only z=0 (Q lo) is consumed
__device__ half g_AOH[4096 * 1024];
__device__ half g_AOL[4096 * 1024];
__device__ float g_bias2[16 * 2048];          // [h][delta+1023]

// ================= helpers =================
#define SWZ(o) ((o) ^ ((((o) >> 3)) & 0x70))

static __device__ __forceinline__ uint32_t smem_u32(const void* p) {
    uint32_t a;
    asm("{ .reg .u64 t; cvta.to.shared.u64 t, %1; cvt.u32.u64 %0, t; }" : "=r"(a) : "l"(p));
    return a;
}

static __device__ __forceinline__ void ldsm4(uint32_t* r, uint32_t addr) {
    asm volatile("ldmatrix.sync.aligned.m8n8.x4.shared.b16 {%0,%1,%2,%3}, [%4];"
                 : "=r"(r[0]), "=r"(r[1]), "=r"(r[2]), "=r"(r[3]) : "r"(addr));
}
static __device__ __forceinline__ void ldsm4t(uint32_t* r, uint32_t addr) {
    asm volatile("ldmatrix.sync.aligned.m8n8.x4.trans.shared.b16 {%0,%1,%2,%3}, [%4];"
                 : "=r"(r[0]), "=r"(r[1]), "=r"(r[2]), "=r"(r[3]) : "r"(addr));
}

static __device__ __forceinline__ void hmma(float* c, const uint32_t* a, const uint32_t* b) {
    asm volatile(
        "mma.sync.aligned.m16n8k16.row.col.f32.f16.f16.f32 "
        "{%0,%1,%2,%3}, {%4,%5,%6,%7}, {%8,%9}, {%0,%1,%2,%3};"
        : "+f"(c[0]), "+f"(c[1]), "+f"(c[2]), "+f"(c[3])
        : "r"(a[0]), "r"(a[1]), "r"(a[2]), "r"(a[3]), "r"(b[0]), "r"(b[1]));
}

#define CP_ASYNC16(dst, src) \
    asm volatile("cp.async.cg.shared.global [%0], [%1], 16;" :: "r"(dst), "l"(src))
#define CP_COMMIT() asm volatile("cp.async.commit_group;" ::: "memory")
#define CP_WAIT(n)  asm volatile("cp.async.wait_group %0;" :: "n"(n) : "memory")

static __device__ __forceinline__ uint32_t pack_hi(float a, float b) {
    __half2 h = __floats2half2_rn(a, b);
    return *(uint32_t*)&h;
}
static __device__ __forceinline__ uint32_t pack_lo(float a, float b) {
    __half2 h = __floats2half2_rn(a, b);
    float2 f = __half22float2(h);
    __half2 l = __floats2half2_rn(a - f.x, b - f.y);
    return *(uint32_t*)&l;
}

// ================= split fp32 -> fp16 hi/lo =================
__global__ __launch_bounds__(256)
void split_kernel(const float* __restrict__ in, half* __restrict__ hi,
                  half* __restrict__ lo, int n4)
{
    int t = blockIdx.x * blockDim.x + threadIdx.x;
    if (t >= n4) return;
    float4 v = ((const float4*)in)[t];
    uint2 h, l;
    h.x = pack_hi(v.x, v.y); h.y = pack_hi(v.z, v.w);
    l.x = pack_lo(v.x, v.y); l.y = pack_lo(v.z, v.w);
    ((uint2*)hi)[t] = h;
    ((uint2*)lo)[t] = l;
}

__global__ __launch_bounds__(256)
void split_w_kernel(const float* __restrict__ w0, const float* __restrict__ w1,
                    const float* __restrict__ w2, const float* __restrict__ w3,
                    half* __restrict__ hi, half* __restrict__ lo)
{
    int t = blockIdx.x * blockDim.x + threadIdx.x;
    if (t >= 262144) return;
    int z = blockIdx.z;
    const float* in = (z == 0) ? w0 : (z == 1) ? w1 : (z == 2) ? w2 : w3;
    float4 v = ((const float4*)in)[t];
    uint2 h, l;
    h.x = pack_hi(v.x, v.y); h.y = pack_hi(v.z, v.w);
    l.x = pack_lo(v.x, v.y); l.y = pack_lo(v.z, v.w);
    ((uint2*)(hi + (size_t)z * 1048576))[t] = h;
    ((uint2*)(lo + (size_t)z * 1048576))[t] = l;
}

// ================= bias table =================
__global__ void bias_kernel(const float* __restrict__ rel_bias) {
    int t = blockIdx.x * blockDim.x + threadIdx.x;
    if (t >= 2048) return;
    int delta = t - 1023;
    int n = -delta;
    int ret = (n < 0) ? 16 : 0;
    n = (n < 0) ? -n : n;
    int bucket;
    if (n < 8) {
        bucket = ret + n;
    } else {
        float x = (logf((float)n * 0.125f) / logf(16.0f)) * 8.0f;
        int v = 8 + (int)x;
        if (v > 15) v = 15;
        bucket = ret + v;
    }
    #pragma unroll
    for (int h = 0; h < HEADS; h++)
        g_bias2[h * 2048 + t] = rel_bias[bucket * HEADS + h];
}

// ================= proj GEMM: C = A * B^T, fp16 split ==================
// CTA 128x128, BK=64, 512 threads (16 warps, 4m x 4n), 3-stage cp.async ring.
// fill for stage cc+2 issued BEFORE compute(cc) so 2 fill-groups overlap compute.
// EPI 1 (QKV): z=0 (Q): 3-pass, stores hi+lo. z=1,2 (K,V): 2-pass, hi only.
// EPI 0 (out): 2-pass ((Ah+Al)*Bh), B lo never loaded.
#define PSTAGE 65536   // A hi 16K | A lo 16K | B hi 16K | B lo 16K
#define PSMEM  (3 * PSTAGE)

template <int EPI>
__global__ __launch_bounds__(512, 1)
void proj_gemm(const half* __restrict__ AH, const half* __restrict__ AL,
               const half* __restrict__ BH, const half* __restrict__ BL,
               float* __restrict__ Cf, half* __restrict__ CH, half* __restrict__ CL)
{
    extern __shared__ char smem[];
    const uint32_t sb = smem_u32(smem);
    const int tid = threadIdx.x;
    const int lane = tid & 31, wid = tid >> 5;
    const int wm = wid >> 2, wn = wid & 3;
    const int m0 = blockIdx.y * 128;
    const int n0 = blockIdx.x * 128;
    const int z = blockIdx.z;
    const bool use_bl = (EPI == 1) && (z == 0);   // third pass only for Q

    const half* BHp = BH;
    const half* BLp = BL;
    half* CHp = CH;
    half* CLp = CL;
    if (EPI == 1) {
        BHp += (size_t)z * 1048576; BLp += (size_t)z * 1048576;
        CHp += (size_t)z * 4194304; CLp += (size_t)z * 4194304;
    }

    float c[2][4][4];
    #pragma unroll
    for (int i = 0; i < 2; i++)
        #pragma unroll
        for (int j = 0; j < 4; j++)
            #pragma unroll
            for (int u = 0; u < 4; u++) c[i][j][u] = 0.0f;

    auto fill = [&](int st, int k0) {
        uint32_t base = sb + st * PSTAGE;
        #pragma unroll
        for (int j = 0; j < 2; j++) {
            int idx = j * 512 + tid;
            int row = idx >> 3, seg = idx & 7;
            uint32_t sw = SWZ((uint32_t)(row * 128 + seg * 16));
            CP_ASYNC16(base + sw,         AH  + (size_t)(m0 + row) * 1024 + k0 + seg * 8);
            CP_ASYNC16(base + 16384 + sw, AL  + (size_t)(m0 + row) * 1024 + k0 + seg * 8);
            CP_ASYNC16(base + 32768 + sw, BHp + (size_t)(n0 + row) * 1024 + k0 + seg * 8);
            if (use_bl)
                CP_ASYNC16(base + 49152 + sw, BLp + (size_t)(n0 + row) * 1024 + k0 + seg * 8);
        }
        CP_COMMIT();
    };

    const int a_row = wm * 32 + (lane & 15);
    const int a_cb = (lane >> 4) * 16;
    const int b_row = wn * 32 + ((lane >> 4) & 1) * 8 + (lane & 7);
    const int b_cb = ((lane >> 3) & 1) * 16;

    auto compute = [&](int st) {
        const uint32_t base = sb + st * PSTAGE;
        const uint32_t aH = base, aL = base + 16384;
        const uint32_t bH = base + 32768, bL = base + 49152;
        #pragma unroll
        for (int ks = 0; ks < 4; ks++) {
            uint32_t fah[2][4], fal[2][4], fbh[2][4], fbl[2][4];
            #pragma unroll
            for (int mt = 0; mt < 2; mt++) {
                uint32_t off = SWZ((uint32_t)((a_row + mt * 16) * 128 + ks * 32 + a_cb));
                ldsm4(fah[mt], aH + off);
                ldsm4(fal[mt], aL + off);
            }
            #pragma unroll
            for (int nt2 = 0; nt2 < 2; nt2++) {
                uint32_t off = SWZ((uint32_t)((b_row + nt2 * 16) * 128 + ks * 32 + b_cb));
                ldsm4(fbh[nt2], bH + off);
                if (use_bl) ldsm4(fbl[nt2], bL + off);
            }
            #pragma unroll
            for (int mt = 0; mt < 2; mt++)
                #pragma unroll
                for (int nt = 0; nt < 4; nt++) {
                    const uint32_t* ph = &fbh[nt >> 1][(nt & 1) * 2];
                    hmma(c[mt][nt], fah[mt], ph);
                    hmma(c[mt][nt], fal[mt], ph);
                    if (use_bl) {
                        const uint32_t* pl = &fbl[nt >> 1][(nt & 1) * 2];
                        hmma(c[mt][nt], fah[mt], pl);
                    }
                }
        }
    };

    fill(0, 0);
    fill(1, 64);
    #pragma unroll 1
    for (int cc = 0; cc < 16; cc++) {
        if (cc + 1 < 16) { CP_WAIT(1); } else { CP_WAIT(0); }
        __syncthreads();
        // fill BEFORE compute: buffer (cc+2)%3 == (cc-1)%3 is free after the
        // barrier; during compute(cc) two fill-groups (cc+1, cc+2) are in flight.
        if (cc + 2 < 16) fill((cc + 2) % 3, (cc + 2) * 64);
        compute(cc % 3);
    }

    #pragma unroll
    for (int mt = 0; mt < 2; mt++)
        #pragma unroll
        for (int nt = 0; nt < 4; nt++) {
            int mg = m0 + wm * 32 + mt * 16 + (lane >> 2);
            int ng = n0 + wn * 32 + nt * 8 + 2 * (lane & 3);
            float* cf = c[mt][nt];
            if (EPI == 0) {
                *(float2*)(Cf + (size_t)mg * 1024 + ng)       = make_float2(cf[0], cf[1]);
                *(float2*)(Cf + (size_t)(mg + 8) * 1024 + ng) = make_float2(cf[2], cf[3]);
            } else {
                int h = ng >> 6, d = ng & 63;
                int b = mg >> 10, s = mg & 1023;
                size_t i0 = ((size_t)(b * HEADS + h) * 1024 + s) * 64 + d;
                size_t i1 = i0 + 8 * 64;
                *(uint32_t*)(CHp + i0) = pack_hi(cf[0], cf[1]);
                *(uint32_t*)(CHp + i1) = pack_hi(cf[2], cf[3]);
                if (z == 0) {   // lo only consumed for Q
                    *(uint32_t*)(CLp + i0) = pack_lo(cf[0], cf[1]);
                    *(uint32_t*)(CLp + i1) = pack_lo(cf[2], cf[3]);
                }
            }
        }
}

// ================= fused attention: 32 q-rows/CTA, 512 threads ================
// K/V chunks hi-only in a 4-buffer ring, prefetch depth 3.
#define OFF_SC   0                       // 32 rows x 4096B
#define OFF_QH   131072                  // 4096
#define OFF_QL   135168                  // 4096
#define OFF_KB0  139264                  // 4 x 16384 ring
#define OFF_BIAS 204800                  // 1056 floats (pad 4352)
#define OFF_MASK 209152                  // 4096
#define OFF_RED  213248                  // 8192
#define ASMEM    221440

#define KB(i)  (OFF_KB0 + (i) * 16384)
// fp32 score element access, swizzled by row within 128B windows
#define SCADDR(row, off) (OFF_SC + (row) * 4096 + ((off) ^ (((row) & 7) << 4)))
// fp16 P access (first 2048B of each row)
#define PADDR(row, jb) (OFF_SC + (row) * 4096 + (((((jb) >> 4) ^ ((row) & 7))) << 4) + ((jb) & 15))

__global__ __launch_bounds__(512, 1)
void attn_fused(const int* __restrict__ mask, float* __restrict__ weights,
                const half* __restrict__ QKVH, const half* __restrict__ QKVL,
                half* __restrict__ AOH, half* __restrict__ AOL)
{
    extern __shared__ char smem[];
    const uint32_t sb = smem_u32(smem);
    const int tid = threadIdx.x;
    const int lane = tid & 31, wid = tid >> 5;
    const int bh = blockIdx.y;
    const int b = bh >> 4, h = bh & 15;
    const int q0 = blockIdx.x * 32;

    // hi-only chunk fill: 128 rows x 64 cols from stream zsel (1=K, 2=V)
    auto fill_chunk = [&](int buf, int zsel, int r0) {
        #pragma unroll
        for (int it = 0; it < 2; it++) {
            int g = it * 512 + tid;
            int row = g >> 3, seg = g & 7;
            uint32_t sw = SWZ((uint32_t)(row * 128 + seg * 16));
            CP_ASYNC16(sb + KB(buf) + sw,
                       QKVH + ((size_t)(zsel * BHD + bh) * 1024 + r0 + row) * 64 + seg * 8);
        }
        CP_COMMIT();
    };

    // Q hi+lo fill (group 0), then K chunks 0,1,2 (groups 1..3)
    if (tid < 256) {
        int row = tid >> 3, seg = tid & 7;
        uint32_t sw = SWZ((uint32_t)(row * 128 + seg * 16));
        CP_ASYNC16(sb + OFF_QH + sw, QKVH + ((size_t)bh * 1024 + q0 + row) * 64 + seg * 8);
        CP_ASYNC16(sb + OFF_QL + sw, QKVL + ((size_t)bh * 1024 + q0 + row) * 64 + seg * 8);
    }
    CP_COMMIT();
    fill_chunk(0, 1, 0);
    fill_chunk(1, 1, 128);
    fill_chunk(2, 1, 256);
    for (int i = tid; i < 1056; i += 512)
        *(float*)(smem + OFF_BIAS + i * 4) = g_bias2[h * 2048 + 992 - q0 + i];
    for (int i = tid; i < 1024; i += 512)
        *(int*)(smem + OFF_MASK + i * 4) = mask[b * 1024 + i];

    // ---- scores: 8 chunks of 128 j; warps = 2 m-tiles x 8 j-slices ----
    // 2-pass: (Qh + Ql) * Kh
    const int wm1 = wid >> 3;
    const int wjj = (wid & 7) * 16;
    const int a_cb = (lane >> 4) * 16;
    const int b_row1 = ((lane >> 4) & 1) * 8 + (lane & 7);
    const int b_cb = ((lane >> 3) & 1) * 16;

    #pragma unroll 1
    for (int jc = 0; jc < 8; jc++) {
        const int j0 = jc * 128;
        if (jc < 6)      { CP_WAIT(2); }
        else if (jc == 6){ CP_WAIT(1); }
        else             { CP_WAIT(0); }
        __syncthreads();
        if (jc + 3 < 8) fill_chunk((jc + 3) & 3, 1, j0 + 384);
        const uint32_t kbuf = KB(jc & 3);

        float c2[2][4];
        #pragma unroll
        for (int j = 0; j < 2; j++)
            #pragma unroll
            for (int u = 0; u < 4; u++) c2[j][u] = 0.0f;

        #pragma unroll
        for (int ks = 0; ks < 4; ks++) {
            uint32_t fah[4], fal[4], fbh[4];
            uint32_t offA = SWZ((uint32_t)((wm1 * 16 + (lane & 15)) * 128 + ks * 32 + a_cb));
            ldsm4(fah, sb + OFF_QH + offA);
            ldsm4(fal, sb + OFF_QL + offA);
            uint32_t offB = SWZ((uint32_t)((wjj + b_row1) * 128 + ks * 32 + b_cb));
            ldsm4(fbh, sb + kbuf + offB);
            #pragma unroll
            for (int nt = 0; nt < 2; nt++) {
                hmma(c2[nt], fah, &fbh[nt * 2]);
                hmma(c2[nt], fal, &fbh[nt * 2]);
            }
        }

        #pragma unroll
        for (int nt = 0; nt < 2; nt++) {
            int ml0 = wm1 * 16 + (lane >> 2), ml1 = ml0 + 8;
            int jg = j0 + wjj + nt * 8 + 2 * (lane & 3);
            float* cf = c2[nt];
            int mk0 = *(int*)(smem + OFF_MASK + jg * 4);
            int mk1 = *(int*)(smem + OFF_MASK + (jg + 1) * 4);
            float v0 = cf[0] * 0.125f + *(float*)(smem + OFF_BIAS + (jg - ml0 + 31) * 4);
            float v1 = cf[1] * 0.125f + *(float*)(smem + OFF_BIAS + (jg + 1 - ml0 + 31) * 4);
            float v2 = cf[2] * 0.125f + *(float*)(smem + OFF_BIAS + (jg - ml1 + 31) * 4);
            float v3 = cf[3] * 0.125f + *(float*)(smem + OFF_BIAS + (jg + 1 - ml1 + 31) * 4);
            if (mk0 == 0) { v0 = -1e9f; v2 = -1e9f; }
            if (mk1 == 0) { v1 = -1e9f; v3 = -1e9f; }
            *(float2*)(smem + SCADDR(ml0, (uint32_t)jg * 4)) = make_float2(v0, v1);
            *(float2*)(smem + SCADDR(ml1, (uint32_t)jg * 4)) = make_float2(v2, v3);
        }
    }

    // Prefetch V chunks 0,1,2 into bufs 0,1,2 — safe without a sync: every
    // warp has passed the jc=7 top __syncthreads, which post-dates all reads
    // of K chunks 4,5,6 (bufs 0,1,2). Buf 3 (K chunk 7) may still be in use.
    fill_chunk(0, 2, 0);
    fill_chunk(1, 2, 128);
    fill_chunk(2, 2, 256);
    __syncthreads();   // chunk-7 score writes + buf3 reads complete

    // ---- softmax: 2 rows per warp; float4 I/O; P fp16 into own row ----
    // V fills for chunks 0-2 land under this phase.
    #pragma unroll 1
    for (int t = 0; t < 2; t++) {
        int r = wid * 2 + t;
        float x[32];
        float mx = -1e30f;
        #pragma unroll
        for (int i = 0; i < 8; i++) {
            float4 f = *(float4*)(smem + SCADDR(r, (uint32_t)(16 * lane + 512 * i)));
            x[4 * i] = f.x; x[4 * i + 1] = f.y; x[4 * i + 2] = f.z; x[4 * i + 3] = f.w;
            mx = fmaxf(mx, fmaxf(fmaxf(f.x, f.y), fmaxf(f.z, f.w)));
        }
        #pragma unroll
        for (int o = 16; o > 0; o >>= 1)
            mx = fmaxf(mx, __shfl_xor_sync(0xFFFFFFFF, mx, o));
        float s = 0.0f;
        #pragma unroll
        for (int i = 0; i < 32; i++) { x[i] = __expf(x[i] - mx); s += x[i]; }
        #pragma unroll
        for (int o = 16; o > 0; o >>= 1)
            s += __shfl_xor_sync(0xFFFFFFFF, s, o);
        float inv = 1.0f / s;
        float* wrow = weights + ((size_t)bh * 1024 + q0 + r) * 1024;
        #pragma unroll
        for (int i = 0; i < 8; i++) {
            float p0 = x[4 * i] * inv, p1 = x[4 * i + 1] * inv;
            float p2 = x[4 * i + 2] * inv, p3 = x[4 * i + 3] * inv;
            *(float4*)(wrow + 4 * lane + 128 * i) = make_float4(p0, p1, p2, p3);
            uint32_t jb = (uint32_t)(4 * lane + 128 * i) * 2;
            *(uint2*)(smem + PADDR(r, jb)) = make_uint2(pack_hi(p0, p1), pack_hi(p2, p3));
        }
    }
    __syncthreads();

    // ---- AV: 8 chunks of 128 s; 1-pass Ph*Vh; warps = 2m x 2kh x 4d ----
    const int wm2 = wid >> 3;
    const int kh2 = (wid >> 2) & 1;
    const int nt_w = wid & 3;
    const int tb_row = (lane & 7) + ((lane >> 3) & 1) * 8;
    const int tb_cb = ((lane >> 4) & 1) * 16;
    float cav[2][4];
    #pragma unroll
    for (int j = 0; j < 2; j++)
        #pragma unroll
        for (int u = 0; u < 4; u++) cav[j][u] = 0.0f;

    #pragma unroll 1
    for (int sc = 0; sc < 8; sc++) {
        const int s0 = sc * 128;
        if (sc < 6)      { CP_WAIT(2); }
        else if (sc == 6){ CP_WAIT(1); }
        else             { CP_WAIT(0); }
        __syncthreads();
        if (sc + 3 < 8) fill_chunk((sc + 3) & 3, 2, s0 + 384);
        const uint32_t vbuf = KB(sc & 3);

        #pragma unroll
        for (int ks = 0; ks < 4; ks++) {
            int kl = kh2 * 64 + ks * 16;
            uint32_t fp[4], fvh[4];
            uint32_t prow = wm2 * 16 + (lane & 15);
            uint32_t jb = (uint32_t)(s0 + kl) * 2 + a_cb;
            ldsm4(fp, sb + PADDR(prow, jb));
            uint32_t offB = SWZ((uint32_t)((kl + tb_row) * 128 + nt_w * 32 + tb_cb));
            ldsm4t(fvh, sb + vbuf + offB);
            hmma(cav[0], fp, &fvh[0]);
            hmma(cav[1], fp, &fvh[2]);
        }
    }
    __syncthreads();

    // reduce kh=1 into kh=0, then epilogue
    if (kh2 == 1) {
        #pragma unroll
        for (int f = 0; f < 2; f++)
            *(float4*)(smem + OFF_RED + (((wm2 * 4 + nt_w) * 2 + f) * 32 + lane) * 16) =
                make_float4(cav[f][0], cav[f][1], cav[f][2], cav[f][3]);
    }
    __syncthreads();
    if (kh2 == 0) {
        #pragma unroll
        for (int f = 0; f < 2; f++) {
            float4 r4 = *(float4*)(smem + OFF_RED + (((wm2 * 4 + nt_w) * 2 + f) * 32 + lane) * 16);
            cav[f][0] += r4.x; cav[f][1] += r4.y; cav[f][2] += r4.z; cav[f][3] += r4.w;
            int srow = q0 + wm2 * 16 + (lane >> 2);
            int d = nt_w * 16 + f * 8 + 2 * (lane & 3);
            size_t i0 = ((size_t)(b * 1024 + srow)) * 1024 + h * 64 + d;
            size_t i1 = i0 + (size_t)8 * 1024;
            *(uint32_t*)(AOH + i0) = pack_hi(cav[f][0], cav[f][1]);
            *(uint32_t*)(AOL + i0) = pack_lo(cav[f][0], cav[f][1]);
            *(uint32_t*)(AOH + i1) = pack_hi(cav[f][2], cav[f][3]);
            *(uint32_t*)(AOL + i1) = pack_lo(cav[f][2], cav[f][3]);
        }
    }
}

// ================= launch =================
extern "C" void kernel_launch(void* const* d_in, const int* in_sizes, int n_in,
                              void* d_out, int out_size)
{
    const float* hs   = (const float*)d_in[0];
    const int*   mask = (const int*)  d_in[1];
    const float* Wq   = (const float*)d_in[2];
    const float* Wk   = (const float*)d_in[3];
    const float* Wv   = (const float*)d_in[4];
    const float* Wo   = (const float*)d_in[5];
    const float* rb   = (const float*)d_in[6];
    float* out = (float*)d_out;
    float* weights = out + (size_t)BATCH * S_LEN * DMODEL;

    half *hsH, *hsL, *WH, *WL, *QKVH, *QKVL, *AOH, *AOL;
    cudaGetSymbolAddress((void**)&hsH,  g_hsH);
    cudaGetSymbolAddress((void**)&hsL,  g_hsL);
    cudaGetSymbolAddress((void**)&WH,   g_WH);
    cudaGetSymbolAddress((void**)&WL,   g_WL);
    cudaGetSymbolAddress((void**)&QKVH, g_QKVH);
    cudaGetSymbolAddress((void**)&QKVL, g_QKVL);
    cudaGetSymbolAddress((void**)&AOH,  g_AOH);
    cudaGetSymbolAddress((void**)&AOL,  g_AOL);

    cudaFuncSetAttribute(proj_gemm<0>, cudaFuncAttributeMaxDynamicSharedMemorySize, PSMEM);
    cudaFuncSetAttribute(proj_gemm<1>, cudaFuncAttributeMaxDynamicSharedMemorySize, PSMEM);
    cudaFuncSetAttribute(attn_fused, cudaFuncAttributeMaxDynamicSharedMemorySize, ASMEM);

    bias_kernel<<<8, 256>>>(rb);
    split_kernel<<<4096, 256>>>(hs, hsH, hsL, 1048576);
    split_w_kernel<<<dim3(1024, 1, 4), 256>>>(Wq, Wk, Wv, Wo, WH, WL);

    // Q/K/V projections (z selects weight + dst slice; Q 3-pass, K/V 2-pass)
    proj_gemm<1><<<dim3(8, 32, 3), 512, PSMEM>>>(hsH, hsL, WH, WL, nullptr, QKVH, QKVL);

    // fused scores + bias + mask + softmax + weights + AV
    attn_fused<<<dim3(32, 64), 512, ASMEM>>>(mask, weights, QKVH, QKVL, AOH, AOL);

    // output projection (2-pass, Wo hi only)
    proj_gemm<0><<<dim3(8, 32, 1), 512, PSMEM>>>(
        AOH, AOL, WH + 3145728, WL + 3145728, out, nullptr, nullptr);
}

// round 14
// speedup vs baseline: 1.0201x; 1.0201x over previous
#include <cuda_runtime.h>
#include <cuda_fp16.h>
#include <math.h>
#include <stdint.h>

#define S_LEN  1024
#define BATCH  4
#define HEADS  16
#define DKV    64
#define DMODEL 1024
#define BHD    (BATCH * HEADS)

// ---------------- scratch (device globals; no allocation allowed) ----------------
__device__ half g_hsH[4096 * 1024];
__device__ half g_hsL[4096 * 1024];
__device__ half g_WH[4 * 1024 * 1024];        // q,k,v,o
__device__ half g_WL[4 * 1024 * 1024];
__device__ half g_QKVH[3 * BHD * 1024 * 64];  // z: 0 Q, 1 K, 2 V; [bh][s][64]
__device__ half g_QKVL[3 * BHD * 1024 * 64];  // only z=0 (Q lo) is consumed
__device__ half g_AOH[4096 * 1024];
__device__ half g_AOL[4096 * 1024];
__device__ float g_bias2[16 * 2048];          // [h][delta+1023]

// ================= helpers =================
#define SWZ(o) ((o) ^ ((((o) >> 3)) & 0x70))

static __device__ __forceinline__ uint32_t smem_u32(const void* p) {
    uint32_t a;
    asm("{ .reg .u64 t; cvta.to.shared.u64 t, %1; cvt.u32.u64 %0, t; }" : "=r"(a) : "l"(p));
    return a;
}

static __device__ __forceinline__ void ldsm4(uint32_t* r, uint32_t addr) {
    asm volatile("ldmatrix.sync.aligned.m8n8.x4.shared.b16 {%0,%1,%2,%3}, [%4];"
                 : "=r"(r[0]), "=r"(r[1]), "=r"(r[2]), "=r"(r[3]) : "r"(addr));
}
static __device__ __forceinline__ void ldsm4t(uint32_t* r, uint32_t addr) {
    asm volatile("ldmatrix.sync.aligned.m8n8.x4.trans.shared.b16 {%0,%1,%2,%3}, [%4];"
                 : "=r"(r[0]), "=r"(r[1]), "=r"(r[2]), "=r"(r[3]) : "r"(addr));
}

static __device__ __forceinline__ void hmma(float* c, const uint32_t* a, const uint32_t* b) {
    asm volatile(
        "mma.sync.aligned.m16n8k16.row.col.f32.f16.f16.f32 "
        "{%0,%1,%2,%3}, {%4,%5,%6,%7}, {%8,%9}, {%0,%1,%2,%3};"
        : "+f"(c[0]), "+f"(c[1]), "+f"(c[2]), "+f"(c[3])
        : "r"(a[0]), "r"(a[1]), "r"(a[2]), "r"(a[3]), "r"(b[0]), "r"(b[1]));
}

#define CP_ASYNC16(dst, src) \
    asm volatile("cp.async.cg.shared.global [%0], [%1], 16;" :: "r"(dst), "l"(src))
#define CP_COMMIT() asm volatile("cp.async.commit_group;" ::: "memory")
#define CP_WAIT(n)  asm volatile("cp.async.wait_group %0;" :: "n"(n) : "memory")

#define STG_CS_F4(p, a, b, c_, d_) \
    asm volatile("st.global.cs.v4.f32 [%0], {%1,%2,%3,%4};" \
                 :: "l"(p), "f"(a), "f"(b), "f"(c_), "f"(d_) : "memory")

static __device__ __forceinline__ uint32_t pack_hi(float a, float b) {
    __half2 h = __floats2half2_rn(a, b);
    return *(uint32_t*)&h;
}
static __device__ __forceinline__ uint32_t pack_lo(float a, float b) {
    __half2 h = __floats2half2_rn(a, b);
    float2 f = __half22float2(h);
    __half2 l = __floats2half2_rn(a - f.x, b - f.y);
    return *(uint32_t*)&l;
}

// ================= merged split fp32 -> fp16 hi/lo =================
// z=0: hs (1048576 float4). z=1..4: Wq/Wk/Wv/Wo (262144 float4 each).
__global__ __launch_bounds__(256)
void split_all_kernel(const float* __restrict__ hs,
                      const float* __restrict__ w0, const float* __restrict__ w1,
                      const float* __restrict__ w2, const float* __restrict__ w3,
                      half* __restrict__ hsH, half* __restrict__ hsL,
                      half* __restrict__ WH, half* __restrict__ WL)
{
    int t = blockIdx.x * blockDim.x + threadIdx.x;
    int z = blockIdx.z;
    const float* in;
    half *hi, *lo;
    int n4;
    if (z == 0) { in = hs; hi = hsH; lo = hsL; n4 = 1048576; }
    else {
        in = (z == 1) ? w0 : (z == 2) ? w1 : (z == 3) ? w2 : w3;
        hi = WH + (size_t)(z - 1) * 1048576;
        lo = WL + (size_t)(z - 1) * 1048576;
        n4 = 262144;
    }
    if (t >= n4) return;
    float4 v = ((const float4*)in)[t];
    uint2 h, l;
    h.x = pack_hi(v.x, v.y); h.y = pack_hi(v.z, v.w);
    l.x = pack_lo(v.x, v.y); l.y = pack_lo(v.z, v.w);
    ((uint2*)hi)[t] = h;
    ((uint2*)lo)[t] = l;
}

// ================= bias table =================
__global__ void bias_kernel(const float* __restrict__ rel_bias) {
    int t = blockIdx.x * blockDim.x + threadIdx.x;
    if (t >= 2048) return;
    int delta = t - 1023;
    int n = -delta;
    int ret = (n < 0) ? 16 : 0;
    n = (n < 0) ? -n : n;
    int bucket;
    if (n < 8) {
        bucket = ret + n;
    } else {
        float x = (logf((float)n * 0.125f) / logf(16.0f)) * 8.0f;
        int v = 8 + (int)x;
        if (v > 15) v = 15;
        bucket = ret + v;
    }
    #pragma unroll
    for (int h = 0; h < HEADS; h++)
        g_bias2[h * 2048 + t] = rel_bias[bucket * HEADS + h];
}

// ================= proj GEMM: C = A * B^T, fp16 split ==================
// CTA 128x128, BK=64, 512 threads (16 warps, 4m x 4n), 3-stage cp.async ring.
// EPI 1 (QKV): z=0 (Q): 3-pass, stores hi+lo. z=1,2 (K,V): 2-pass, hi only.
// EPI 0 (out): 2-pass ((Ah+Al)*Bh), B lo never loaded.
#define PSTAGE 65536   // A hi 16K | A lo 16K | B hi 16K | B lo 16K
#define PSMEM  (3 * PSTAGE)

template <int EPI>
__global__ __launch_bounds__(512, 1)
void proj_gemm(const half* __restrict__ AH, const half* __restrict__ AL,
               const half* __restrict__ BH, const half* __restrict__ BL,
               float* __restrict__ Cf, half* __restrict__ CH, half* __restrict__ CL)
{
    extern __shared__ char smem[];
    const uint32_t sb = smem_u32(smem);
    const int tid = threadIdx.x;
    const int lane = tid & 31, wid = tid >> 5;
    const int wm = wid >> 2, wn = wid & 3;
    const int m0 = blockIdx.y * 128;
    const int n0 = blockIdx.x * 128;
    const int z = blockIdx.z;
    const bool use_bl = (EPI == 1) && (z == 0);   // third pass only for Q

    const half* BHp = BH;
    const half* BLp = BL;
    half* CHp = CH;
    half* CLp = CL;
    if (EPI == 1) {
        BHp += (size_t)z * 1048576; BLp += (size_t)z * 1048576;
        CHp += (size_t)z * 4194304; CLp += (size_t)z * 4194304;
    }

    float c[2][4][4];
    #pragma unroll
    for (int i = 0; i < 2; i++)
        #pragma unroll
        for (int j = 0; j < 4; j++)
            #pragma unroll
            for (int u = 0; u < 4; u++) c[i][j][u] = 0.0f;

    auto fill = [&](int st, int k0) {
        uint32_t base = sb + st * PSTAGE;
        #pragma unroll
        for (int j = 0; j < 2; j++) {
            int idx = j * 512 + tid;
            int row = idx >> 3, seg = idx & 7;
            uint32_t sw = SWZ((uint32_t)(row * 128 + seg * 16));
            CP_ASYNC16(base + sw,         AH  + (size_t)(m0 + row) * 1024 + k0 + seg * 8);
            CP_ASYNC16(base + 16384 + sw, AL  + (size_t)(m0 + row) * 1024 + k0 + seg * 8);
            CP_ASYNC16(base + 32768 + sw, BHp + (size_t)(n0 + row) * 1024 + k0 + seg * 8);
            if (use_bl)
                CP_ASYNC16(base + 49152 + sw, BLp + (size_t)(n0 + row) * 1024 + k0 + seg * 8);
        }
        CP_COMMIT();
    };

    const int a_row = wm * 32 + (lane & 15);
    const int a_cb = (lane >> 4) * 16;
    const int b_row = wn * 32 + ((lane >> 4) & 1) * 8 + (lane & 7);
    const int b_cb = ((lane >> 3) & 1) * 16;

    auto compute = [&](int st) {
        const uint32_t base = sb + st * PSTAGE;
        const uint32_t aH = base, aL = base + 16384;
        const uint32_t bH = base + 32768, bL = base + 49152;
        #pragma unroll
        for (int ks = 0; ks < 4; ks++) {
            uint32_t fah[2][4], fal[2][4], fbh[2][4], fbl[2][4];
            #pragma unroll
            for (int mt = 0; mt < 2; mt++) {
                uint32_t off = SWZ((uint32_t)((a_row + mt * 16) * 128 + ks * 32 + a_cb));
                ldsm4(fah[mt], aH + off);
                ldsm4(fal[mt], aL + off);
            }
            #pragma unroll
            for (int nt2 = 0; nt2 < 2; nt2++) {
                uint32_t off = SWZ((uint32_t)((b_row + nt2 * 16) * 128 + ks * 32 + b_cb));
                ldsm4(fbh[nt2], bH + off);
                if (use_bl) ldsm4(fbl[nt2], bL + off);
            }
            #pragma unroll
            for (int mt = 0; mt < 2; mt++)
                #pragma unroll
                for (int nt = 0; nt < 4; nt++) {
                    const uint32_t* ph = &fbh[nt >> 1][(nt & 1) * 2];
                    hmma(c[mt][nt], fah[mt], ph);
                    hmma(c[mt][nt], fal[mt], ph);
                    if (use_bl) {
                        const uint32_t* pl = &fbl[nt >> 1][(nt & 1) * 2];
                        hmma(c[mt][nt], fah[mt], pl);
                    }
                }
        }
    };

    fill(0, 0);
    fill(1, 64);
    #pragma unroll 1
    for (int cc = 0; cc < 16; cc++) {
        if (cc + 1 < 16) { CP_WAIT(1); } else { CP_WAIT(0); }
        __syncthreads();
        compute(cc % 3);
        if (cc + 2 < 16) fill((cc + 2) % 3, (cc + 2) * 64);
    }

    #pragma unroll
    for (int mt = 0; mt < 2; mt++)
        #pragma unroll
        for (int nt = 0; nt < 4; nt++) {
            int mg = m0 + wm * 32 + mt * 16 + (lane >> 2);
            int ng = n0 + wn * 32 + nt * 8 + 2 * (lane & 3);
            float* cf = c[mt][nt];
            if (EPI == 0) {
                *(float2*)(Cf + (size_t)mg * 1024 + ng)       = make_float2(cf[0], cf[1]);
                *(float2*)(Cf + (size_t)(mg + 8) * 1024 + ng) = make_float2(cf[2], cf[3]);
            } else {
                int h = ng >> 6, d = ng & 63;
                int b = mg >> 10, s = mg & 1023;
                size_t i0 = ((size_t)(b * HEADS + h) * 1024 + s) * 64 + d;
                size_t i1 = i0 + 8 * 64;
                *(uint32_t*)(CHp + i0) = pack_hi(cf[0], cf[1]);
                *(uint32_t*)(CHp + i1) = pack_hi(cf[2], cf[3]);
                if (z == 0) {   // lo only consumed for Q
                    *(uint32_t*)(CLp + i0) = pack_lo(cf[0], cf[1]);
                    *(uint32_t*)(CLp + i1) = pack_lo(cf[2], cf[3]);
                }
            }
        }
}

// ================= fused attention: 32 q-rows/CTA, 512 threads ================
// K/V chunks hi-only in a 4-buffer ring, prefetch depth 3.
#define OFF_SC   0                       // 32 rows x 4096B
#define OFF_QH   131072                  // 4096
#define OFF_QL   135168                  // 4096
#define OFF_KB0  139264                  // 4 x 16384 ring
#define OFF_BIAS 204800                  // 1056 floats (pad 4352)
#define OFF_MASK 209152                  // 4096
#define OFF_RED  213248                  // 8192
#define ASMEM    221440

#define KB(i)  (OFF_KB0 + (i) * 16384)
// fp32 score element access, swizzled by row within 128B windows
#define SCADDR(row, off) (OFF_SC + (row) * 4096 + ((off) ^ (((row) & 7) << 4)))
// fp16 P access (first 2048B of each row)
#define PADDR(row, jb) (OFF_SC + (row) * 4096 + (((((jb) >> 4) ^ ((row) & 7))) << 4) + ((jb) & 15))

__global__ __launch_bounds__(512, 1)
void attn_fused(const int* __restrict__ mask, float* __restrict__ weights,
                const half* __restrict__ QKVH, const half* __restrict__ QKVL,
                half* __restrict__ AOH, half* __restrict__ AOL)
{
    extern __shared__ char smem[];
    const uint32_t sb = smem_u32(smem);
    const int tid = threadIdx.x;
    const int lane = tid & 31, wid = tid >> 5;
    const int bh = blockIdx.y;
    const int b = bh >> 4, h = bh & 15;
    const int q0 = blockIdx.x * 32;

    // hi-only chunk fill: 128 rows x 64 cols from stream zsel (1=K, 2=V)
    auto fill_chunk = [&](int buf, int zsel, int r0) {
        #pragma unroll
        for (int it = 0; it < 2; it++) {
            int g = it * 512 + tid;
            int row = g >> 3, seg = g & 7;
            uint32_t sw = SWZ((uint32_t)(row * 128 + seg * 16));
            CP_ASYNC16(sb + KB(buf) + sw,
                       QKVH + ((size_t)(zsel * BHD + bh) * 1024 + r0 + row) * 64 + seg * 8);
        }
        CP_COMMIT();
    };

    // Q hi+lo fill (group 0), then K chunks 0,1,2 (groups 1..3)
    if (tid < 256) {
        int row = tid >> 3, seg = tid & 7;
        uint32_t sw = SWZ((uint32_t)(row * 128 + seg * 16));
        CP_ASYNC16(sb + OFF_QH + sw, QKVH + ((size_t)bh * 1024 + q0 + row) * 64 + seg * 8);
        CP_ASYNC16(sb + OFF_QL + sw, QKVL + ((size_t)bh * 1024 + q0 + row) * 64 + seg * 8);
    }
    CP_COMMIT();
    fill_chunk(0, 1, 0);
    fill_chunk(1, 1, 128);
    fill_chunk(2, 1, 256);
    for (int i = tid; i < 1056; i += 512)
        *(float*)(smem + OFF_BIAS + i * 4) = g_bias2[h * 2048 + 992 - q0 + i];
    for (int i = tid; i < 1024; i += 512)
        *(int*)(smem + OFF_MASK + i * 4) = mask[b * 1024 + i];

    // ---- scores: 8 chunks of 128 j; warps = 2 m-tiles x 8 j-slices ----
    // 2-pass: (Qh + Ql) * Kh
    const int wm1 = wid >> 3;
    const int wjj = (wid & 7) * 16;
    const int a_cb = (lane >> 4) * 16;
    const int b_row1 = ((lane >> 4) & 1) * 8 + (lane & 7);
    const int b_cb = ((lane >> 3) & 1) * 16;

    #pragma unroll 1
    for (int jc = 0; jc < 8; jc++) {
        const int j0 = jc * 128;
        if (jc < 6)      { CP_WAIT(2); }
        else if (jc == 6){ CP_WAIT(1); }
        else             { CP_WAIT(0); }
        __syncthreads();
        if (jc + 3 < 8) fill_chunk((jc + 3) & 3, 1, j0 + 384);
        const uint32_t kbuf = KB(jc & 3);

        float c2[2][4];
        #pragma unroll
        for (int j = 0; j < 2; j++)
            #pragma unroll
            for (int u = 0; u < 4; u++) c2[j][u] = 0.0f;

        #pragma unroll
        for (int ks = 0; ks < 4; ks++) {
            uint32_t fah[4], fal[4], fbh[4];
            uint32_t offA = SWZ((uint32_t)((wm1 * 16 + (lane & 15)) * 128 + ks * 32 + a_cb));
            ldsm4(fah, sb + OFF_QH + offA);
            ldsm4(fal, sb + OFF_QL + offA);
            uint32_t offB = SWZ((uint32_t)((wjj + b_row1) * 128 + ks * 32 + b_cb));
            ldsm4(fbh, sb + kbuf + offB);
            #pragma unroll
            for (int nt = 0; nt < 2; nt++) {
                hmma(c2[nt], fah, &fbh[nt * 2]);
                hmma(c2[nt], fal, &fbh[nt * 2]);
            }
        }

        #pragma unroll
        for (int nt = 0; nt < 2; nt++) {
            int ml0 = wm1 * 16 + (lane >> 2), ml1 = ml0 + 8;
            int jg = j0 + wjj + nt * 8 + 2 * (lane & 3);
            float* cf = c2[nt];
            int mk0 = *(int*)(smem + OFF_MASK + jg * 4);
            int mk1 = *(int*)(smem + OFF_MASK + (jg + 1) * 4);
            float v0 = cf[0] * 0.125f + *(float*)(smem + OFF_BIAS + (jg - ml0 + 31) * 4);
            float v1 = cf[1] * 0.125f + *(float*)(smem + OFF_BIAS + (jg + 1 - ml0 + 31) * 4);
            float v2 = cf[2] * 0.125f + *(float*)(smem + OFF_BIAS + (jg - ml1 + 31) * 4);
            float v3 = cf[3] * 0.125f + *(float*)(smem + OFF_BIAS + (jg + 1 - ml1 + 31) * 4);
            if (mk0 == 0) { v0 = -1e9f; v2 = -1e9f; }
            if (mk1 == 0) { v1 = -1e9f; v3 = -1e9f; }
            *(float2*)(smem + SCADDR(ml0, (uint32_t)jg * 4)) = make_float2(v0, v1);
            *(float2*)(smem + SCADDR(ml1, (uint32_t)jg * 4)) = make_float2(v2, v3);
        }
    }

    // Prefetch V chunks 0,1,2 into bufs 0,1,2 — safe without a sync: every
    // warp has passed the jc=7 top __syncthreads, which post-dates all reads
    // of K chunks 4,5,6 (bufs 0,1,2). Buf 3 (K chunk 7) may still be in use.
    fill_chunk(0, 2, 0);
    fill_chunk(1, 2, 128);
    fill_chunk(2, 2, 256);
    __syncthreads();   // chunk-7 score writes + buf3 reads complete

    // ---- softmax: 2 rows per warp; float4 I/O; P fp16 into own row ----
    // Weights stream out with evict-first (.cs) — never re-read.
    #pragma unroll 1
    for (int t = 0; t < 2; t++) {
        int r = wid * 2 + t;
        float x[32];
        float mx = -1e30f;
        #pragma unroll
        for (int i = 0; i < 8; i++) {
            float4 f = *(float4*)(smem + SCADDR(r, (uint32_t)(16 * lane + 512 * i)));
            x[4 * i] = f.x; x[4 * i + 1] = f.y; x[4 * i + 2] = f.z; x[4 * i + 3] = f.w;
            mx = fmaxf(mx, fmaxf(fmaxf(f.x, f.y), fmaxf(f.z, f.w)));
        }
        #pragma unroll
        for (int o = 16; o > 0; o >>= 1)
            mx = fmaxf(mx, __shfl_xor_sync(0xFFFFFFFF, mx, o));
        float s = 0.0f;
        #pragma unroll
        for (int i = 0; i < 32; i++) { x[i] = __expf(x[i] - mx); s += x[i]; }
        #pragma unroll
        for (int o = 16; o > 0; o >>= 1)
            s += __shfl_xor_sync(0xFFFFFFFF, s, o);
        float inv = 1.0f / s;
        float* wrow = weights + ((size_t)bh * 1024 + q0 + r) * 1024;
        #pragma unroll
        for (int i = 0; i < 8; i++) {
            float p0 = x[4 * i] * inv, p1 = x[4 * i + 1] * inv;
            float p2 = x[4 * i + 2] * inv, p3 = x[4 * i + 3] * inv;
            STG_CS_F4(wrow + 4 * lane + 128 * i, p0, p1, p2, p3);
            uint32_t jb = (uint32_t)(4 * lane + 128 * i) * 2;
            *(uint2*)(smem + PADDR(r, jb)) = make_uint2(pack_hi(p0, p1), pack_hi(p2, p3));
        }
    }
    __syncthreads();

    // ---- AV: 8 chunks of 128 s; 1-pass Ph*Vh; warps = 2m x 2kh x 4d ----
    const int wm2 = wid >> 3;
    const int kh2 = (wid >> 2) & 1;
    const int nt_w = wid & 3;
    const int tb_row = (lane & 7) + ((lane >> 3) & 1) * 8;
    const int tb_cb = ((lane >> 4) & 1) * 16;
    float cav[2][4];
    #pragma unroll
    for (int j = 0; j < 2; j++)
        #pragma unroll
        for (int u = 0; u < 4; u++) cav[j][u] = 0.0f;

    #pragma unroll 1
    for (int sc = 0; sc < 8; sc++) {
        const int s0 = sc * 128;
        if (sc < 6)      { CP_WAIT(2); }
        else if (sc == 6){ CP_WAIT(1); }
        else             { CP_WAIT(0); }
        __syncthreads();
        if (sc + 3 < 8) fill_chunk((sc + 3) & 3, 2, s0 + 384);
        const uint32_t vbuf = KB(sc & 3);

        #pragma unroll
        for (int ks = 0; ks < 4; ks++) {
            int kl = kh2 * 64 + ks * 16;
            uint32_t fp[4], fvh[4];
            uint32_t prow = wm2 * 16 + (lane & 15);
            uint32_t jb = (uint32_t)(s0 + kl) * 2 + a_cb;
            ldsm4(fp, sb + PADDR(prow, jb));
            uint32_t offB = SWZ((uint32_t)((kl + tb_row) * 128 + nt_w * 32 + tb_cb));
            ldsm4t(fvh, sb + vbuf + offB);
            hmma(cav[0], fp, &fvh[0]);
            hmma(cav[1], fp, &fvh[2]);
        }
    }
    __syncthreads();

    // reduce kh=1 into kh=0, then epilogue
    if (kh2 == 1) {
        #pragma unroll
        for (int f = 0; f < 2; f++)
            *(float4*)(smem + OFF_RED + (((wm2 * 4 + nt_w) * 2 + f) * 32 + lane) * 16) =
                make_float4(cav[f][0], cav[f][1], cav[f][2], cav[f][3]);
    }
    __syncthreads();
    if (kh2 == 0) {
        #pragma unroll
        for (int f = 0; f < 2; f++) {
            float4 r4 = *(float4*)(smem + OFF_RED + (((wm2 * 4 + nt_w) * 2 + f) * 32 + lane) * 16);
            cav[f][0] += r4.x; cav[f][1] += r4.y; cav[f][2] += r4.z; cav[f][3] += r4.w;
            int srow = q0 + wm2 * 16 + (lane >> 2);
            int d = nt_w * 16 + f * 8 + 2 * (lane & 3);
            size_t i0 = ((size_t)(b * 1024 + srow)) * 1024 + h * 64 + d;
            size_t i1 = i0 + (size_t)8 * 1024;
            *(uint32_t*)(AOH + i0) = pack_hi(cav[f][0], cav[f][1]);
            *(uint32_t*)(AOL + i0) = pack_lo(cav[f][0], cav[f][1]);
            *(uint32_t*)(AOH + i1) = pack_hi(cav[f][2], cav[f][3]);
            *(uint32_t*)(AOL + i1) = pack_lo(cav[f][2], cav[f][3]);
        }
    }
}

// ================= launch =================
extern "C" void kernel_launch(void* const* d_in, const int* in_sizes, int n_in,
                              void* d_out, int out_size)
{
    const float* hs   = (const float*)d_in[0];
    const int*   mask = (const int*)  d_in[1];
    const float* Wq   = (const float*)d_in[2];
    const float* Wk   = (const float*)d_in[3];
    const float* Wv   = (const float*)d_in[4];
    const float* Wo   = (const float*)d_in[5];
    const float* rb   = (const float*)d_in[6];
    float* out = (float*)d_out;
    float* weights = out + (size_t)BATCH * S_LEN * DMODEL;

    half *hsH, *hsL, *WH, *WL, *QKVH, *QKVL, *AOH, *AOL;
    cudaGetSymbolAddress((void**)&hsH,  g_hsH);
    cudaGetSymbolAddress((void**)&hsL,  g_hsL);
    cudaGetSymbolAddress((void**)&WH,   g_WH);
    cudaGetSymbolAddress((void**)&WL,   g_WL);
    cudaGetSymbolAddress((void**)&QKVH, g_QKVH);
    cudaGetSymbolAddress((void**)&QKVL, g_QKVL);
    cudaGetSymbolAddress((void**)&AOH,  g_AOH);
    cudaGetSymbolAddress((void**)&AOL,  g_AOL);

    cudaFuncSetAttribute(proj_gemm<0>, cudaFuncAttributeMaxDynamicSharedMemorySize, PSMEM);
    cudaFuncSetAttribute(proj_gemm<1>, cudaFuncAttributeMaxDynamicSharedMemorySize, PSMEM);
    cudaFuncSetAttribute(attn_fused, cudaFuncAttributeMaxDynamicSharedMemorySize, ASMEM);

    bias_kernel<<<8, 256>>>(rb);
    split_all_kernel<<<dim3(4096, 1, 5), 256>>>(hs, Wq, Wk, Wv, Wo, hsH, hsL, WH, WL);

    // Q/K/V projections (z selects weight + dst slice; Q 3-pass, K/V 2-pass)
    proj_gemm<1><<<dim3(8, 32, 3), 512, PSMEM>>>(hsH, hsL, WH, WL, nullptr, QKVH, QKVL);

    // fused scores + bias + mask + softmax + weights + AV
    attn_fused<<<dim3(32, 64), 512, ASMEM>>>(mask, weights, QKVH, QKVL, AOH, AOL);

    // output projection (2-pass, Wo hi only)
    proj_gemm<0><<<dim3(8, 32, 1), 512, PSMEM>>>(
        AOH, AOL, WH + 3145728, WL + 3145728, out, nullptr, nullptr);
}

// round 15
// speedup vs baseline: 1.0579x; 1.0370x over previous
#include <cuda_runtime.h>
#include <cuda_fp16.h>
#include <math.h>
#include <stdint.h>

#define S_LEN  1024
#define BATCH  4
#define HEADS  16
#define DKV    64
#define DMODEL 1024
#define BHD    (BATCH * HEADS)

// ---------------- scratch (device globals; no allocation allowed) ----------------
__device__ half g_hsH[4096 * 1024];
__device__ half g_hsL[4096 * 1024];
__device__ half g_WH[4 * 1024 * 1024];        // q,k,v,o
__device__ half g_WL[4 * 1024 * 1024];
__device__ half g_QKVH[3 * BHD * 1024 * 64];  // z: 0 Q (pre-scaled by 1/8), 1 K, 2 V
__device__ half g_QKVL[3 * BHD * 1024 * 64];  // only z=0 (Q lo) is consumed
__device__ half g_AOH[4096 * 1024];
__device__ half g_AOL[4096 * 1024];
__device__ float g_bias2[16 * 2048];          // [h][delta+1023]

// ================= helpers =================
#define SWZ(o) ((o) ^ ((((o) >> 3)) & 0x70))

static __device__ __forceinline__ uint32_t smem_u32(const void* p) {
    uint32_t a;
    asm("{ .reg .u64 t; cvta.to.shared.u64 t, %1; cvt.u32.u64 %0, t; }" : "=r"(a) : "l"(p));
    return a;
}

static __device__ __forceinline__ void ldsm4(uint32_t* r, uint32_t addr) {
    asm volatile("ldmatrix.sync.aligned.m8n8.x4.shared.b16 {%0,%1,%2,%3}, [%4];"
                 : "=r"(r[0]), "=r"(r[1]), "=r"(r[2]), "=r"(r[3]) : "r"(addr));
}
static __device__ __forceinline__ void ldsm4t(uint32_t* r, uint32_t addr) {
    asm volatile("ldmatrix.sync.aligned.m8n8.x4.trans.shared.b16 {%0,%1,%2,%3}, [%4];"
                 : "=r"(r[0]), "=r"(r[1]), "=r"(r[2]), "=r"(r[3]) : "r"(addr));
}

static __device__ __forceinline__ void hmma(float* c, const uint32_t* a, const uint32_t* b) {
    asm volatile(
        "mma.sync.aligned.m16n8k16.row.col.f32.f16.f16.f32 "
        "{%0,%1,%2,%3}, {%4,%5,%6,%7}, {%8,%9}, {%0,%1,%2,%3};"
        : "+f"(c[0]), "+f"(c[1]), "+f"(c[2]), "+f"(c[3])
        : "r"(a[0]), "r"(a[1]), "r"(a[2]), "r"(a[3]), "r"(b[0]), "r"(b[1]));
}

#define CP_ASYNC16(dst, src) \
    asm volatile("cp.async.cg.shared.global [%0], [%1], 16;" :: "r"(dst), "l"(src))
#define CP_COMMIT() asm volatile("cp.async.commit_group;" ::: "memory")
#define CP_WAIT(n)  asm volatile("cp.async.wait_group %0;" :: "n"(n) : "memory")

#define STG_CS_F4(p, a, b, c_, d_) \
    asm volatile("st.global.cs.v4.f32 [%0], {%1,%2,%3,%4};" \
                 :: "l"(p), "f"(a), "f"(b), "f"(c_), "f"(d_) : "memory")

static __device__ __forceinline__ uint32_t pack_hi(float a, float b) {
    __half2 h = __floats2half2_rn(a, b);
    return *(uint32_t*)&h;
}
static __device__ __forceinline__ uint32_t pack_lo(float a, float b) {
    __half2 h = __floats2half2_rn(a, b);
    float2 f = __half22float2(h);
    __half2 l = __floats2half2_rn(a - f.x, b - f.y);
    return *(uint32_t*)&l;
}

// ================= merged split fp32 -> fp16 hi/lo =================
__global__ __launch_bounds__(256)
void split_all_kernel(const float* __restrict__ hs,
                      const float* __restrict__ w0, const float* __restrict__ w1,
                      const float* __restrict__ w2, const float* __restrict__ w3,
                      half* __restrict__ hsH, half* __restrict__ hsL,
                      half* __restrict__ WH, half* __restrict__ WL)
{
    int t = blockIdx.x * blockDim.x + threadIdx.x;
    int z = blockIdx.z;
    const float* in;
    half *hi, *lo;
    int n4;
    if (z == 0) { in = hs; hi = hsH; lo = hsL; n4 = 1048576; }
    else {
        in = (z == 1) ? w0 : (z == 2) ? w1 : (z == 3) ? w2 : w3;
        hi = WH + (size_t)(z - 1) * 1048576;
        lo = WL + (size_t)(z - 1) * 1048576;
        n4 = 262144;
    }
    if (t >= n4) return;
    float4 v = ((const float4*)in)[t];
    uint2 h, l;
    h.x = pack_hi(v.x, v.y); h.y = pack_hi(v.z, v.w);
    l.x = pack_lo(v.x, v.y); l.y = pack_lo(v.z, v.w);
    ((uint2*)hi)[t] = h;
    ((uint2*)lo)[t] = l;
}

// ================= bias table =================
__global__ void bias_kernel(const float* __restrict__ rel_bias) {
    int t = blockIdx.x * blockDim.x + threadIdx.x;
    if (t >= 2048) return;
    int delta = t - 1023;
    int n = -delta;
    int ret = (n < 0) ? 16 : 0;
    n = (n < 0) ? -n : n;
    int bucket;
    if (n < 8) {
        bucket = ret + n;
    } else {
        float x = (logf((float)n * 0.125f) / logf(16.0f)) * 8.0f;
        int v = 8 + (int)x;
        if (v > 15) v = 15;
        bucket = ret + v;
    }
    #pragma unroll
    for (int h = 0; h < HEADS; h++)
        g_bias2[h * 2048 + t] = rel_bias[bucket * HEADS + h];
}

// ================= proj GEMM: C = A * B^T, fp16 split ==================
// CTA 128x128, BK=64, 512 threads (16 warps, 4m x 4n), 3-stage cp.async ring.
// EPI 1 (QKV): z=0 (Q): 3-pass, stores hi+lo PRE-SCALED by 0.125 (exact).
//              z=1,2 (K,V): 2-pass, hi only.
// EPI 0 (out): 2-pass ((Ah+Al)*Bh), B lo never loaded.
#define PSTAGE 65536   // A hi 16K | A lo 16K | B hi 16K | B lo 16K
#define PSMEM  (3 * PSTAGE)

template <int EPI>
__global__ __launch_bounds__(512, 1)
void proj_gemm(const half* __restrict__ AH, const half* __restrict__ AL,
               const half* __restrict__ BH, const half* __restrict__ BL,
               float* __restrict__ Cf, half* __restrict__ CH, half* __restrict__ CL)
{
    extern __shared__ char smem[];
    const uint32_t sb = smem_u32(smem);
    const int tid = threadIdx.x;
    const int lane = tid & 31, wid = tid >> 5;
    const int wm = wid >> 2, wn = wid & 3;
    const int m0 = blockIdx.y * 128;
    const int n0 = blockIdx.x * 128;
    const int z = blockIdx.z;
    const bool use_bl = (EPI == 1) && (z == 0);   // third pass only for Q

    const half* BHp = BH;
    const half* BLp = BL;
    half* CHp = CH;
    half* CLp = CL;
    if (EPI == 1) {
        BHp += (size_t)z * 1048576; BLp += (size_t)z * 1048576;
        CHp += (size_t)z * 4194304; CLp += (size_t)z * 4194304;
    }

    float c[2][4][4];
    #pragma unroll
    for (int i = 0; i < 2; i++)
        #pragma unroll
        for (int j = 0; j < 4; j++)
            #pragma unroll
            for (int u = 0; u < 4; u++) c[i][j][u] = 0.0f;

    auto fill = [&](int st, int k0) {
        uint32_t base = sb + st * PSTAGE;
        #pragma unroll
        for (int j = 0; j < 2; j++) {
            int idx = j * 512 + tid;
            int row = idx >> 3, seg = idx & 7;
            uint32_t sw = SWZ((uint32_t)(row * 128 + seg * 16));
            CP_ASYNC16(base + sw,         AH  + (size_t)(m0 + row) * 1024 + k0 + seg * 8);
            CP_ASYNC16(base + 16384 + sw, AL  + (size_t)(m0 + row) * 1024 + k0 + seg * 8);
            CP_ASYNC16(base + 32768 + sw, BHp + (size_t)(n0 + row) * 1024 + k0 + seg * 8);
            if (use_bl)
                CP_ASYNC16(base + 49152 + sw, BLp + (size_t)(n0 + row) * 1024 + k0 + seg * 8);
        }
        CP_COMMIT();
    };

    const int a_row = wm * 32 + (lane & 15);
    const int a_cb = (lane >> 4) * 16;
    const int b_row = wn * 32 + ((lane >> 4) & 1) * 8 + (lane & 7);
    const int b_cb = ((lane >> 3) & 1) * 16;

    auto compute = [&](int st) {
        const uint32_t base = sb + st * PSTAGE;
        const uint32_t aH = base, aL = base + 16384;
        const uint32_t bH = base + 32768, bL = base + 49152;
        #pragma unroll
        for (int ks = 0; ks < 4; ks++) {
            uint32_t fah[2][4], fal[2][4], fbh[2][4], fbl[2][4];
            #pragma unroll
            for (int mt = 0; mt < 2; mt++) {
                uint32_t off = SWZ((uint32_t)((a_row + mt * 16) * 128 + ks * 32 + a_cb));
                ldsm4(fah[mt], aH + off);
                ldsm4(fal[mt], aL + off);
            }
            #pragma unroll
            for (int nt2 = 0; nt2 < 2; nt2++) {
                uint32_t off = SWZ((uint32_t)((b_row + nt2 * 16) * 128 + ks * 32 + b_cb));
                ldsm4(fbh[nt2], bH + off);
                if (use_bl) ldsm4(fbl[nt2], bL + off);
            }
            #pragma unroll
            for (int mt = 0; mt < 2; mt++)
                #pragma unroll
                for (int nt = 0; nt < 4; nt++) {
                    const uint32_t* ph = &fbh[nt >> 1][(nt & 1) * 2];
                    hmma(c[mt][nt], fah[mt], ph);
                    hmma(c[mt][nt], fal[mt], ph);
                    if (use_bl) {
                        const uint32_t* pl = &fbl[nt >> 1][(nt & 1) * 2];
                        hmma(c[mt][nt], fah[mt], pl);
                    }
                }
        }
    };

    fill(0, 0);
    fill(1, 64);
    #pragma unroll 1
    for (int cc = 0; cc < 16; cc++) {
        if (cc + 1 < 16) { CP_WAIT(1); } else { CP_WAIT(0); }
        __syncthreads();
        compute(cc % 3);
        if (cc + 2 < 16) fill((cc + 2) % 3, (cc + 2) * 64);
    }

    #pragma unroll
    for (int mt = 0; mt < 2; mt++)
        #pragma unroll
        for (int nt = 0; nt < 4; nt++) {
            int mg = m0 + wm * 32 + mt * 16 + (lane >> 2);
            int ng = n0 + wn * 32 + nt * 8 + 2 * (lane & 3);
            float* cf = c[mt][nt];
            if (EPI == 0) {
                *(float2*)(Cf + (size_t)mg * 1024 + ng)       = make_float2(cf[0], cf[1]);
                *(float2*)(Cf + (size_t)(mg + 8) * 1024 + ng) = make_float2(cf[2], cf[3]);
            } else {
                int h = ng >> 6, d = ng & 63;
                int b = mg >> 10, s = mg & 1023;
                size_t i0 = ((size_t)(b * HEADS + h) * 1024 + s) * 64 + d;
                size_t i1 = i0 + 8 * 64;
                if (z == 0) {   // Q: pre-scale by 1/8 (exact), store hi+lo
                    float q0 = cf[0] * 0.125f, q1 = cf[1] * 0.125f;
                    float q2 = cf[2] * 0.125f, q3 = cf[3] * 0.125f;
                    *(uint32_t*)(CHp + i0) = pack_hi(q0, q1);
                    *(uint32_t*)(CHp + i1) = pack_hi(q2, q3);
                    *(uint32_t*)(CLp + i0) = pack_lo(q0, q1);
                    *(uint32_t*)(CLp + i1) = pack_lo(q2, q3);
                } else {
                    *(uint32_t*)(CHp + i0) = pack_hi(cf[0], cf[1]);
                    *(uint32_t*)(CHp + i1) = pack_hi(cf[2], cf[3]);
                }
            }
        }
}

// ================= fused attention: 32 q-rows/CTA, 512 threads ================
// K/V chunks hi-only in a 4-buffer ring, prefetch depth 3. Q held in registers.
#define OFF_SC   0                       // 32 rows x 4096B
#define OFF_QH   131072                  // 4096
#define OFF_QL   135168                  // 4096
#define OFF_KB0  139264                  // 4 x 16384 ring
#define OFF_BIAS 204800                  // 1056 floats (pad 4352)
#define OFF_MASK 209152                  // 4096
#define OFF_RED  213248                  // 8192
#define ASMEM    221440

#define KB(i)  (OFF_KB0 + (i) * 16384)
// fp32 score element access, swizzled by row within 128B windows
#define SCADDR(row, off) (OFF_SC + (row) * 4096 + ((off) ^ (((row) & 7) << 4)))
// fp16 P access (first 2048B of each row)
#define PADDR(row, jb) (OFF_SC + (row) * 4096 + (((((jb) >> 4) ^ ((row) & 7))) << 4) + ((jb) & 15))

__global__ __launch_bounds__(512, 1)
void attn_fused(const int* __restrict__ mask, float* __restrict__ weights,
                const half* __restrict__ QKVH, const half* __restrict__ QKVL,
                half* __restrict__ AOH, half* __restrict__ AOL)
{
    extern __shared__ char smem[];
    const uint32_t sb = smem_u32(smem);
    const int tid = threadIdx.x;
    const int lane = tid & 31, wid = tid >> 5;
    const int bh = blockIdx.y;
    const int b = bh >> 4, h = bh & 15;
    const int q0 = blockIdx.x * 32;

    // hi-only chunk fill: 128 rows x 64 cols from stream zsel (1=K, 2=V)
    auto fill_chunk = [&](int buf, int zsel, int r0) {
        #pragma unroll
        for (int it = 0; it < 2; it++) {
            int g = it * 512 + tid;
            int row = g >> 3, seg = g & 7;
            uint32_t sw = SWZ((uint32_t)(row * 128 + seg * 16));
            CP_ASYNC16(sb + KB(buf) + sw,
                       QKVH + ((size_t)(zsel * BHD + bh) * 1024 + r0 + row) * 64 + seg * 8);
        }
        CP_COMMIT();
    };

    // Q hi+lo fill (group 0), then K chunks 0,1,2 (groups 1..3)
    if (tid < 256) {
        int row = tid >> 3, seg = tid & 7;
        uint32_t sw = SWZ((uint32_t)(row * 128 + seg * 16));
        CP_ASYNC16(sb + OFF_QH + sw, QKVH + ((size_t)bh * 1024 + q0 + row) * 64 + seg * 8);
        CP_ASYNC16(sb + OFF_QL + sw, QKVL + ((size_t)bh * 1024 + q0 + row) * 64 + seg * 8);
    }
    CP_COMMIT();
    fill_chunk(0, 1, 0);
    fill_chunk(1, 1, 128);
    fill_chunk(2, 1, 256);
    for (int i = tid; i < 1056; i += 512)
        *(float*)(smem + OFF_BIAS + i * 4) = g_bias2[h * 2048 + 992 - q0 + i];
    for (int i = tid; i < 1024; i += 512)
        *(int*)(smem + OFF_MASK + i * 4) = mask[b * 1024 + i];

    // ---- scores: 8 chunks of 128 j; warps = 2 m-tiles x 8 j-slices ----
    // 2-pass: (Qh + Ql) * Kh; Q pre-scaled by 1/8 at projection time.
    const int wm1 = wid >> 3;
    const int wjj = (wid & 7) * 16;
    const int a_cb = (lane >> 4) * 16;
    const int b_row1 = ((lane >> 4) & 1) * 8 + (lane & 7);
    const int b_cb = ((lane >> 3) & 1) * 16;

    // Peel: wait for Q + K0, then hoist Q into registers for all 4 ks.
    CP_WAIT(2);
    __syncthreads();
    uint32_t fah_r[4][4], fal_r[4][4];
    #pragma unroll
    for (int ks = 0; ks < 4; ks++) {
        uint32_t offA = SWZ((uint32_t)((wm1 * 16 + (lane & 15)) * 128 + ks * 32 + a_cb));
        ldsm4(fah_r[ks], sb + OFF_QH + offA);
        ldsm4(fal_r[ks], sb + OFF_QL + offA);
    }

    #pragma unroll 1
    for (int jc = 0; jc < 8; jc++) {
        const int j0 = jc * 128;
        if (jc > 0) {
            if (jc < 6)      { CP_WAIT(2); }
            else if (jc == 6){ CP_WAIT(1); }
            else             { CP_WAIT(0); }
            __syncthreads();
        }
        if (jc + 3 < 8) fill_chunk((jc + 3) & 3, 1, j0 + 384);
        const uint32_t kbuf = KB(jc & 3);

        float c2[2][4];
        #pragma unroll
        for (int j = 0; j < 2; j++)
            #pragma unroll
            for (int u = 0; u < 4; u++) c2[j][u] = 0.0f;

        #pragma unroll
        for (int ks = 0; ks < 4; ks++) {
            uint32_t fbh[4];
            uint32_t offB = SWZ((uint32_t)((wjj + b_row1) * 128 + ks * 32 + b_cb));
            ldsm4(fbh, sb + kbuf + offB);
            #pragma unroll
            for (int nt = 0; nt < 2; nt++) {
                hmma(c2[nt], fah_r[ks], &fbh[nt * 2]);
                hmma(c2[nt], fal_r[ks], &fbh[nt * 2]);
            }
        }

        #pragma unroll
        for (int nt = 0; nt < 2; nt++) {
            int ml0 = wm1 * 16 + (lane >> 2), ml1 = ml0 + 8;
            int jg = j0 + wjj + nt * 8 + 2 * (lane & 3);
            float* cf = c2[nt];
            int mk0 = *(int*)(smem + OFF_MASK + jg * 4);
            int mk1 = *(int*)(smem + OFF_MASK + (jg + 1) * 4);
            float v0 = cf[0] + *(float*)(smem + OFF_BIAS + (jg - ml0 + 31) * 4);
            float v1 = cf[1] + *(float*)(smem + OFF_BIAS + (jg + 1 - ml0 + 31) * 4);
            float v2 = cf[2] + *(float*)(smem + OFF_BIAS + (jg - ml1 + 31) * 4);
            float v3 = cf[3] + *(float*)(smem + OFF_BIAS + (jg + 1 - ml1 + 31) * 4);
            if (mk0 == 0) { v0 = -1e9f; v2 = -1e9f; }
            if (mk1 == 0) { v1 = -1e9f; v3 = -1e9f; }
            *(float2*)(smem + SCADDR(ml0, (uint32_t)jg * 4)) = make_float2(v0, v1);
            *(float2*)(smem + SCADDR(ml1, (uint32_t)jg * 4)) = make_float2(v2, v3);
        }
    }

    // Prefetch V chunks 0,1,2 into bufs 0,1,2 — safe without a sync: every
    // warp has passed the jc=7 top __syncthreads, which post-dates all reads
    // of K chunks 4,5,6 (bufs 0,1,2). Buf 3 (K chunk 7) may still be in use.
    fill_chunk(0, 2, 0);
    fill_chunk(1, 2, 128);
    fill_chunk(2, 2, 256);
    __syncthreads();   // chunk-7 score writes + buf3 reads complete

    // ---- softmax: 2 rows per warp; float4 I/O; P fp16 into own row ----
    // Weights stream out with evict-first (.cs) — never re-read.
    #pragma unroll 1
    for (int t = 0; t < 2; t++) {
        int r = wid * 2 + t;
        float x[32];
        float mx = -1e30f;
        #pragma unroll
        for (int i = 0; i < 8; i++) {
            float4 f = *(float4*)(smem + SCADDR(r, (uint32_t)(16 * lane + 512 * i)));
            x[4 * i] = f.x; x[4 * i + 1] = f.y; x[4 * i + 2] = f.z; x[4 * i + 3] = f.w;
            mx = fmaxf(mx, fmaxf(fmaxf(f.x, f.y), fmaxf(f.z, f.w)));
        }
        #pragma unroll
        for (int o = 16; o > 0; o >>= 1)
            mx = fmaxf(mx, __shfl_xor_sync(0xFFFFFFFF, mx, o));
        float s = 0.0f;
        #pragma unroll
        for (int i = 0; i < 32; i++) { x[i] = __expf(x[i] - mx); s += x[i]; }
        #pragma unroll
        for (int o = 16; o > 0; o >>= 1)
            s += __shfl_xor_sync(0xFFFFFFFF, s, o);
        float inv = 1.0f / s;
        float* wrow = weights + ((size_t)bh * 1024 + q0 + r) * 1024;
        #pragma unroll
        for (int i = 0; i < 8; i++) {
            float p0 = x[4 * i] * inv, p1 = x[4 * i + 1] * inv;
            float p2 = x[4 * i + 2] * inv, p3 = x[4 * i + 3] * inv;
            STG_CS_F4(wrow + 4 * lane + 128 * i, p0, p1, p2, p3);
            uint32_t jb = (uint32_t)(4 * lane + 128 * i) * 2;
            *(uint2*)(smem + PADDR(r, jb)) = make_uint2(pack_hi(p0, p1), pack_hi(p2, p3));
        }
    }
    __syncthreads();

    // ---- AV: 8 chunks of 128 s; 1-pass Ph*Vh; warps = 2m x 2kh x 4d ----
    const int wm2 = wid >> 3;
    const int kh2 = (wid >> 2) & 1;
    const int nt_w = wid & 3;
    const int tb_row = (lane & 7) + ((lane >> 3) & 1) * 8;
    const int tb_cb = ((lane >> 4) & 1) * 16;
    float cav[2][4];
    #pragma unroll
    for (int j = 0; j < 2; j++)
        #pragma unroll
        for (int u = 0; u < 4; u++) cav[j][u] = 0.0f;

    #pragma unroll 1
    for (int sc = 0; sc < 8; sc++) {
        const int s0 = sc * 128;
        if (sc < 6)      { CP_WAIT(2); }
        else if (sc == 6){ CP_WAIT(1); }
        else             { CP_WAIT(0); }
        __syncthreads();
        if (sc + 3 < 8) fill_chunk((sc + 3) & 3, 2, s0 + 384);
        const uint32_t vbuf = KB(sc & 3);

        #pragma unroll
        for (int ks = 0; ks < 4; ks++) {
            int kl = kh2 * 64 + ks * 16;
            uint32_t fp[4], fvh[4];
            uint32_t prow = wm2 * 16 + (lane & 15);
            uint32_t jb = (uint32_t)(s0 + kl) * 2 + a_cb;
            ldsm4(fp, sb + PADDR(prow, jb));
            uint32_t offB = SWZ((uint32_t)((kl + tb_row) * 128 + nt_w * 32 + tb_cb));
            ldsm4t(fvh, sb + vbuf + offB);
            hmma(cav[0], fp, &fvh[0]);
            hmma(cav[1], fp, &fvh[2]);
        }
    }
    __syncthreads();

    // reduce kh=1 into kh=0, then epilogue
    if (kh2 == 1) {
        #pragma unroll
        for (int f = 0; f < 2; f++)
            *(float4*)(smem + OFF_RED + (((wm2 * 4 + nt_w) * 2 + f) * 32 + lane) * 16) =
                make_float4(cav[f][0], cav[f][1], cav[f][2], cav[f][3]);
    }
    __syncthreads();
    if (kh2 == 0) {
        #pragma unroll
        for (int f = 0; f < 2; f++) {
            float4 r4 = *(float4*)(smem + OFF_RED + (((wm2 * 4 + nt_w) * 2 + f) * 32 + lane) * 16);
            cav[f][0] += r4.x; cav[f][1] += r4.y; cav[f][2] += r4.z; cav[f][3] += r4.w;
            int srow = q0 + wm2 * 16 + (lane >> 2);
            int d = nt_w * 16 + f * 8 + 2 * (lane & 3);
            size_t i0 = ((size_t)(b * 1024 + srow)) * 1024 + h * 64 + d;
            size_t i1 = i0 + (size_t)8 * 1024;
            *(uint32_t*)(AOH + i0) = pack_hi(cav[f][0], cav[f][1]);
            *(uint32_t*)(AOL + i0) = pack_lo(cav[f][0], cav[f][1]);
            *(uint32_t*)(AOH + i1) = pack_hi(cav[f][2], cav[f][3]);
            *(uint32_t*)(AOL + i1) = pack_lo(cav[f][2], cav[f][3]);
        }
    }
}

// ================= launch =================
extern "C" void kernel_launch(void* const* d_in, const int* in_sizes, int n_in,
                              void* d_out, int out_size)
{
    const float* hs   = (const float*)d_in[0];
    const int*   mask = (const int*)  d_in[1];
    const float* Wq   = (const float*)d_in[2];
    const float* Wk   = (const float*)d_in[3];
    const float* Wv   = (const float*)d_in[4];
    const float* Wo   = (const float*)d_in[5];
    const float* rb   = (const float*)d_in[6];
    float* out = (float*)d_out;
    float* weights = out + (size_t)BATCH * S_LEN * DMODEL;

    half *hsH, *hsL, *WH, *WL, *QKVH, *QKVL, *AOH, *AOL;
    cudaGetSymbolAddress((void**)&hsH,  g_hsH);
    cudaGetSymbolAddress((void**)&hsL,  g_hsL);
    cudaGetSymbolAddress((void**)&WH,   g_WH);
    cudaGetSymbolAddress((void**)&WL,   g_WL);
    cudaGetSymbolAddress((void**)&QKVH, g_QKVH);
    cudaGetSymbolAddress((void**)&QKVL, g_QKVL);
    cudaGetSymbolAddress((void**)&AOH,  g_AOH);
    cudaGetSymbolAddress((void**)&AOL,  g_AOL);

    cudaFuncSetAttribute(proj_gemm<0>, cudaFuncAttributeMaxDynamicSharedMemorySize, PSMEM);
    cudaFuncSetAttribute(proj_gemm<1>, cudaFuncAttributeMaxDynamicSharedMemorySize, PSMEM);
    cudaFuncSetAttribute(attn_fused, cudaFuncAttributeMaxDynamicSharedMemorySize, ASMEM);

    bias_kernel<<<8, 256>>>(rb);
    split_all_kernel<<<dim3(4096, 1, 5), 256>>>(hs, Wq, Wk, Wv, Wo, hsH, hsL, WH, WL);

    // Q/K/V projections (z selects weight + dst slice; Q 3-pass, K/V 2-pass)
    proj_gemm<1><<<dim3(8, 32, 3), 512, PSMEM>>>(hsH, hsL, WH, WL, nullptr, QKVH, QKVL);

    // fused scores + bias + mask + softmax + weights + AV
    attn_fused<<<dim3(32, 64), 512, ASMEM>>>(mask, weights, QKVH, QKVL, AOH, AOL);

    // output projection (2-pass, Wo hi only)
    proj_gemm<0><<<dim3(8, 32, 1), 512, PSMEM>>>(
        AOH, AOL, WH + 3145728, WL + 3145728, out, nullptr, nullptr);
}

// round 17
// speedup vs baseline: 1.0635x; 1.0053x over previous
#include <cuda_runtime.h>
#include <cuda_fp16.h>
#include <math.h>
#include <stdint.h>

#define S_LEN  1024
#define BATCH  4
#define HEADS  16
#define DKV    64
#define DMODEL 1024
#define BHD    (BATCH * HEADS)

// ---------------- scratch (device globals; no allocation allowed) ----------------
__device__ half g_hsH[4096 * 1024];
__device__ half g_hsL[4096 * 1024];
__device__ half g_WH[4 * 1024 * 1024];        // q,k,v,o
__device__ half g_WL[4 * 1024 * 1024];
__device__ half g_QKVH[3 * BHD * 1024 * 64];  // z: 0 Q (pre-scaled by 1/8), 1 K, 2 V
__device__ half g_QKVL[3 * BHD * 1024 * 64];  // only z=0 (Q lo) is consumed
__device__ half g_AOH[4096 * 1024];
__device__ half g_AOL[4096 * 1024];
__device__ float g_bias2[16 * 2048];          // [h][delta+1023]

// ================= helpers =================
#define SWZ(o) ((o) ^ ((((o) >> 3)) & 0x70))

static __device__ __forceinline__ uint32_t smem_u32(const void* p) {
    uint32_t a;
    asm("{ .reg .u64 t; cvta.to.shared.u64 t, %1; cvt.u32.u64 %0, t; }" : "=r"(a) : "l"(p));
    return a;
}

static __device__ __forceinline__ void ldsm4(uint32_t* r, uint32_t addr) {
    asm volatile("ldmatrix.sync.aligned.m8n8.x4.shared.b16 {%0,%1,%2,%3}, [%4];"
                 : "=r"(r[0]), "=r"(r[1]), "=r"(r[2]), "=r"(r[3]) : "r"(addr));
}
static __device__ __forceinline__ void ldsm4t(uint32_t* r, uint32_t addr) {
    asm volatile("ldmatrix.sync.aligned.m8n8.x4.trans.shared.b16 {%0,%1,%2,%3}, [%4];"
                 : "=r"(r[0]), "=r"(r[1]), "=r"(r[2]), "=r"(r[3]) : "r"(addr));
}

static __device__ __forceinline__ void hmma(float* c, const uint32_t* a, const uint32_t* b) {
    asm volatile(
        "mma.sync.aligned.m16n8k16.row.col.f32.f16.f16.f32 "
        "{%0,%1,%2,%3}, {%4,%5,%6,%7}, {%8,%9}, {%0,%1,%2,%3};"
        : "+f"(c[0]), "+f"(c[1]), "+f"(c[2]), "+f"(c[3])
        : "r"(a[0]), "r"(a[1]), "r"(a[2]), "r"(a[3]), "r"(b[0]), "r"(b[1]));
}

#define CP_ASYNC16(dst, src) \
    asm volatile("cp.async.cg.shared.global [%0], [%1], 16;" :: "r"(dst), "l"(src))
#define CP_COMMIT() asm volatile("cp.async.commit_group;" ::: "memory")
#define CP_WAIT(n)  asm volatile("cp.async.wait_group %0;" :: "n"(n) : "memory")

#define STG_CS_F4(p, a, b, c_, d_) \
    asm volatile("st.global.cs.v4.f32 [%0], {%1,%2,%3,%4};" \
                 :: "l"(p), "f"(a), "f"(b), "f"(c_), "f"(d_) : "memory")

static __device__ __forceinline__ uint32_t pack_hi(float a, float b) {
    __half2 h = __floats2half2_rn(a, b);
    return *(uint32_t*)&h;
}
static __device__ __forceinline__ uint32_t pack_lo(float a, float b) {
    __half2 h = __floats2half2_rn(a, b);
    float2 f = __half22float2(h);
    __half2 l = __floats2half2_rn(a - f.x, b - f.y);
    return *(uint32_t*)&l;
}

// ================= merged split fp32 -> fp16 hi/lo =================
__global__ __launch_bounds__(256)
void split_all_kernel(const float* __restrict__ hs,
                      const float* __restrict__ w0, const float* __restrict__ w1,
                      const float* __restrict__ w2, const float* __restrict__ w3,
                      half* __restrict__ hsH, half* __restrict__ hsL,
                      half* __restrict__ WH, half* __restrict__ WL)
{
    int t = blockIdx.x * blockDim.x + threadIdx.x;
    int z = blockIdx.z;
    const float* in;
    half *hi, *lo;
    int n4;
    if (z == 0) { in = hs; hi = hsH; lo = hsL; n4 = 1048576; }
    else {
        in = (z == 1) ? w0 : (z == 2) ? w1 : (z == 3) ? w2 : w3;
        hi = WH + (size_t)(z - 1) * 1048576;
        lo = WL + (size_t)(z - 1) * 1048576;
        n4 = 262144;
    }
    if (t >= n4) return;
    float4 v = ((const float4*)in)[t];
    uint2 h, l;
    h.x = pack_hi(v.x, v.y); h.y = pack_hi(v.z, v.w);
    l.x = pack_lo(v.x, v.y); l.y = pack_lo(v.z, v.w);
    ((uint2*)hi)[t] = h;
    ((uint2*)lo)[t] = l;
}

// ================= bias table =================
__global__ void bias_kernel(const float* __restrict__ rel_bias) {
    int t = blockIdx.x * blockDim.x + threadIdx.x;
    if (t >= 2048) return;
    int delta = t - 1023;
    int n = -delta;
    int ret = (n < 0) ? 16 : 0;
    n = (n < 0) ? -n : n;
    int bucket;
    if (n < 8) {
        bucket = ret + n;
    } else {
        float x = (logf((float)n * 0.125f) / logf(16.0f)) * 8.0f;
        int v = 8 + (int)x;
        if (v > 15) v = 15;
        bucket = ret + v;
    }
    #pragma unroll
    for (int h = 0; h < HEADS; h++)
        g_bias2[h * 2048 + t] = rel_bias[bucket * HEADS + h];
}

// ================= proj GEMM: C = A * B^T, fp16 split ==================
// CTA 128x128, BK=64, 512 threads (16 warps, 4m x 4n), 3-stage cp.async ring.
// EPI 1 (QKV): z=0 (Q): 3-pass, stores hi+lo PRE-SCALED by 0.125 (exact).
//              z=1,2 (K,V): 2-pass, hi only.
// EPI 0 (out): 2-pass ((Ah+Al)*Bh), B lo never loaded.
#define PSTAGE 65536   // A hi 16K | A lo 16K | B hi 16K | B lo 16K
#define PSMEM  (3 * PSTAGE)

template <int EPI>
__global__ __launch_bounds__(512, 1)
void proj_gemm(const half* __restrict__ AH, const half* __restrict__ AL,
               const half* __restrict__ BH, const half* __restrict__ BL,
               float* __restrict__ Cf, half* __restrict__ CH, half* __restrict__ CL)
{
    extern __shared__ char smem[];
    const uint32_t sb = smem_u32(smem);
    const int tid = threadIdx.x;
    const int lane = tid & 31, wid = tid >> 5;
    const int wm = wid >> 2, wn = wid & 3;
    const int m0 = blockIdx.y * 128;
    const int n0 = blockIdx.x * 128;
    const int z = blockIdx.z;
    const bool use_bl = (EPI == 1) && (z == 0);   // third pass only for Q

    const half* BHp = BH;
    const half* BLp = BL;
    half* CHp = CH;
    half* CLp = CL;
    if (EPI == 1) {
        BHp += (size_t)z * 1048576; BLp += (size_t)z * 1048576;
        CHp += (size_t)z * 4194304; CLp += (size_t)z * 4194304;
    }

    float c[2][4][4];
    #pragma unroll
    for (int i = 0; i < 2; i++)
        #pragma unroll
        for (int j = 0; j < 4; j++)
            #pragma unroll
            for (int u = 0; u < 4; u++) c[i][j][u] = 0.0f;

    auto fill = [&](int st, int k0) {
        uint32_t base = sb + st * PSTAGE;
        #pragma unroll
        for (int j = 0; j < 2; j++) {
            int idx = j * 512 + tid;
            int row = idx >> 3, seg = idx & 7;
            uint32_t sw = SWZ((uint32_t)(row * 128 + seg * 16));
            CP_ASYNC16(base + sw,         AH  + (size_t)(m0 + row) * 1024 + k0 + seg * 8);
            CP_ASYNC16(base + 16384 + sw, AL  + (size_t)(m0 + row) * 1024 + k0 + seg * 8);
            CP_ASYNC16(base + 32768 + sw, BHp + (size_t)(n0 + row) * 1024 + k0 + seg * 8);
            if (use_bl)
                CP_ASYNC16(base + 49152 + sw, BLp + (size_t)(n0 + row) * 1024 + k0 + seg * 8);
        }
        CP_COMMIT();
    };

    const int a_row = wm * 32 + (lane & 15);
    const int a_cb = (lane >> 4) * 16;
    const int b_row = wn * 32 + ((lane >> 4) & 1) * 8 + (lane & 7);
    const int b_cb = ((lane >> 3) & 1) * 16;

    auto compute = [&](int st) {
        const uint32_t base = sb + st * PSTAGE;
        const uint32_t aH = base, aL = base + 16384;
        const uint32_t bH = base + 32768, bL = base + 49152;
        #pragma unroll
        for (int ks = 0; ks < 4; ks++) {
            uint32_t fah[2][4], fal[2][4], fbh[2][4], fbl[2][4];
            #pragma unroll
            for (int mt = 0; mt < 2; mt++) {
                uint32_t off = SWZ((uint32_t)((a_row + mt * 16) * 128 + ks * 32 + a_cb));
                ldsm4(fah[mt], aH + off);
                ldsm4(fal[mt], aL + off);
            }
            #pragma unroll
            for (int nt2 = 0; nt2 < 2; nt2++) {
                uint32_t off = SWZ((uint32_t)((b_row + nt2 * 16) * 128 + ks * 32 + b_cb));
                ldsm4(fbh[nt2], bH + off);
                if (use_bl) ldsm4(fbl[nt2], bL + off);
            }
            #pragma unroll
            for (int mt = 0; mt < 2; mt++)
                #pragma unroll
                for (int nt = 0; nt < 4; nt++) {
                    const uint32_t* ph = &fbh[nt >> 1][(nt & 1) * 2];
                    hmma(c[mt][nt], fah[mt], ph);
                    hmma(c[mt][nt], fal[mt], ph);
                    if (use_bl) {
                        const uint32_t* pl = &fbl[nt >> 1][(nt & 1) * 2];
                        hmma(c[mt][nt], fah[mt], pl);
                    }
                }
        }
    };

    fill(0, 0);
    fill(1, 64);
    #pragma unroll 1
    for (int cc = 0; cc < 16; cc++) {
        if (cc + 1 < 16) { CP_WAIT(1); } else { CP_WAIT(0); }
        __syncthreads();
        compute(cc % 3);
        if (cc + 2 < 16) fill((cc + 2) % 3, (cc + 2) * 64);
    }

    #pragma unroll
    for (int mt = 0; mt < 2; mt++)
        #pragma unroll
        for (int nt = 0; nt < 4; nt++) {
            int mg = m0 + wm * 32 + mt * 16 + (lane >> 2);
            int ng = n0 + wn * 32 + nt * 8 + 2 * (lane & 3);
            float* cf = c[mt][nt];
            if (EPI == 0) {
                *(float2*)(Cf + (size_t)mg * 1024 + ng)       = make_float2(cf[0], cf[1]);
                *(float2*)(Cf + (size_t)(mg + 8) * 1024 + ng) = make_float2(cf[2], cf[3]);
            } else {
                int h = ng >> 6, d = ng & 63;
                int b = mg >> 10, s = mg & 1023;
                size_t i0 = ((size_t)(b * HEADS + h) * 1024 + s) * 64 + d;
                size_t i1 = i0 + 8 * 64;
                if (z == 0) {   // Q: pre-scale by 1/8 (exact), store hi+lo
                    float q0 = cf[0] * 0.125f, q1 = cf[1] * 0.125f;
                    float q2 = cf[2] * 0.125f, q3 = cf[3] * 0.125f;
                    *(uint32_t*)(CHp + i0) = pack_hi(q0, q1);
                    *(uint32_t*)(CHp + i1) = pack_hi(q2, q3);
                    *(uint32_t*)(CLp + i0) = pack_lo(q0, q1);
                    *(uint32_t*)(CLp + i1) = pack_lo(q2, q3);
                } else {
                    *(uint32_t*)(CHp + i0) = pack_hi(cf[0], cf[1]);
                    *(uint32_t*)(CHp + i1) = pack_hi(cf[2], cf[3]);
                }
            }
        }
}

// ================= fused attention: 32 q-rows/CTA, 512 threads ================
// K/V chunks hi-only in a 4-buffer ring, prefetch depth 3. Q held in registers.
// Split accumulators (hi/lo in scores, even/odd ks in AV) for 2x HMMA ILP.
#define OFF_SC   0                       // 32 rows x 4096B
#define OFF_QH   131072                  // 4096
#define OFF_QL   135168                  // 4096
#define OFF_KB0  139264                  // 4 x 16384 ring
#define OFF_BIAS 204800                  // 1056 floats (pad 4352)
#define OFF_MASK 209152                  // 4096
#define OFF_RED  213248                  // 8192
#define ASMEM    221440

#define KB(i)  (OFF_KB0 + (i) * 16384)
// fp32 score element access, swizzled by row within 128B windows
#define SCADDR(row, off) (OFF_SC + (row) * 4096 + ((off) ^ (((row) & 7) << 4)))
// fp16 P access (first 2048B of each row)
#define PADDR(row, jb) (OFF_SC + (row) * 4096 + (((((jb) >> 4) ^ ((row) & 7))) << 4) + ((jb) & 15))

__global__ __launch_bounds__(512, 1)
void attn_fused(const int* __restrict__ mask, float* __restrict__ weights,
                const half* __restrict__ QKVH, const half* __restrict__ QKVL,
                half* __restrict__ AOH, half* __restrict__ AOL)
{
    extern __shared__ char smem[];
    const uint32_t sb = smem_u32(smem);
    const int tid = threadIdx.x;
    const int lane = tid & 31, wid = tid >> 5;
    const int bh = blockIdx.y;
    const int b = bh >> 4, h = bh & 15;
    const int q0 = blockIdx.x * 32;

    // hi-only chunk fill: 128 rows x 64 cols from stream zsel (1=K, 2=V)
    auto fill_chunk = [&](int buf, int zsel, int r0) {
        #pragma unroll
        for (int it = 0; it < 2; it++) {
            int g = it * 512 + tid;
            int row = g >> 3, seg = g & 7;
            uint32_t sw = SWZ((uint32_t)(row * 128 + seg * 16));
            CP_ASYNC16(sb + KB(buf) + sw,
                       QKVH + ((size_t)(zsel * BHD + bh) * 1024 + r0 + row) * 64 + seg * 8);
        }
        CP_COMMIT();
    };

    // Q hi+lo fill (group 0), then K chunks 0,1,2 (groups 1..3)
    if (tid < 256) {
        int row = tid >> 3, seg = tid & 7;
        uint32_t sw = SWZ((uint32_t)(row * 128 + seg * 16));
        CP_ASYNC16(sb + OFF_QH + sw, QKVH + ((size_t)bh * 1024 + q0 + row) * 64 + seg * 8);
        CP_ASYNC16(sb + OFF_QL + sw, QKVL + ((size_t)bh * 1024 + q0 + row) * 64 + seg * 8);
    }
    CP_COMMIT();
    fill_chunk(0, 1, 0);
    fill_chunk(1, 1, 128);
    fill_chunk(2, 1, 256);
    for (int i = tid; i < 1056; i += 512)
        *(float*)(smem + OFF_BIAS + i * 4) = g_bias2[h * 2048 + 992 - q0 + i];
    for (int i = tid; i < 1024; i += 512)
        *(int*)(smem + OFF_MASK + i * 4) = mask[b * 1024 + i];

    // ---- scores: 8 chunks of 128 j; warps = 2 m-tiles x 8 j-slices ----
    const int wm1 = wid >> 3;
    const int wjj = (wid & 7) * 16;
    const int a_cb = (lane >> 4) * 16;
    const int b_row1 = ((lane >> 4) & 1) * 8 + (lane & 7);
    const int b_cb = ((lane >> 3) & 1) * 16;

    // Peel: wait for Q + K0, then hoist Q into registers for all 4 ks.
    CP_WAIT(2);
    __syncthreads();
    uint32_t fah_r[4][4], fal_r[4][4];
    #pragma unroll
    for (int ks = 0; ks < 4; ks++) {
        uint32_t offA = SWZ((uint32_t)((wm1 * 16 + (lane & 15)) * 128 + ks * 32 + a_cb));
        ldsm4(fah_r[ks], sb + OFF_QH + offA);
        ldsm4(fal_r[ks], sb + OFF_QL + offA);
    }

    #pragma unroll 1
    for (int jc = 0; jc < 8; jc++) {
        const int j0 = jc * 128;
        if (jc > 0) {
            if (jc < 6)      { CP_WAIT(2); }
            else if (jc == 6){ CP_WAIT(1); }
            else             { CP_WAIT(0); }
            __syncthreads();
        }
        if (jc + 3 < 8) fill_chunk((jc + 3) & 3, 1, j0 + 384);
        const uint32_t kbuf = KB(jc & 3);

        float c2h[2][4], c2l[2][4];
        #pragma unroll
        for (int j = 0; j < 2; j++)
            #pragma unroll
            for (int u = 0; u < 4; u++) { c2h[j][u] = 0.0f; c2l[j][u] = 0.0f; }

        #pragma unroll
        for (int ks = 0; ks < 4; ks++) {
            uint32_t fbh[4];
            uint32_t offB = SWZ((uint32_t)((wjj + b_row1) * 128 + ks * 32 + b_cb));
            ldsm4(fbh, sb + kbuf + offB);
            #pragma unroll
            for (int nt = 0; nt < 2; nt++) {
                hmma(c2h[nt], fah_r[ks], &fbh[nt * 2]);
                hmma(c2l[nt], fal_r[ks], &fbh[nt * 2]);
            }
        }

        #pragma unroll
        for (int nt = 0; nt < 2; nt++) {
            int ml0 = wm1 * 16 + (lane >> 2), ml1 = ml0 + 8;
            int jg = j0 + wjj + nt * 8 + 2 * (lane & 3);
            int mk0 = *(int*)(smem + OFF_MASK + jg * 4);
            int mk1 = *(int*)(smem + OFF_MASK + (jg + 1) * 4);
            float v0 = (c2h[nt][0] + c2l[nt][0]) + *(float*)(smem + OFF_BIAS + (jg - ml0 + 31) * 4);
            float v1 = (c2h[nt][1] + c2l[nt][1]) + *(float*)(smem + OFF_BIAS + (jg + 1 - ml0 + 31) * 4);
            float v2 = (c2h[nt][2] + c2l[nt][2]) + *(float*)(smem + OFF_BIAS + (jg - ml1 + 31) * 4);
            float v3 = (c2h[nt][3] + c2l[nt][3]) + *(float*)(smem + OFF_BIAS + (jg + 1 - ml1 + 31) * 4);
            if (mk0 == 0) { v0 = -1e9f; v2 = -1e9f; }
            if (mk1 == 0) { v1 = -1e9f; v3 = -1e9f; }
            *(float2*)(smem + SCADDR(ml0, (uint32_t)jg * 4)) = make_float2(v0, v1);
            *(float2*)(smem + SCADDR(ml1, (uint32_t)jg * 4)) = make_float2(v2, v3);
        }
    }

    // Prefetch V chunks 0,1,2 into bufs 0,1,2 — safe without a sync: every
    // warp has passed the jc=7 top __syncthreads, which post-dates all reads
    // of K chunks 4,5,6 (bufs 0,1,2). Buf 3 (K chunk 7) may still be in use.
    fill_chunk(0, 2, 0);
    fill_chunk(1, 2, 128);
    fill_chunk(2, 2, 256);
    __syncthreads();   // chunk-7 score writes + buf3 reads complete

    // ---- softmax: 2 rows per warp; float4 I/O; P fp16 into own row ----
    // Weights stream out with evict-first (.cs) — never re-read.
    #pragma unroll 1
    for (int t = 0; t < 2; t++) {
        int r = wid * 2 + t;
        float x[32];
        float mx = -1e30f;
        #pragma unroll
        for (int i = 0; i < 8; i++) {
            float4 f = *(float4*)(smem + SCADDR(r, (uint32_t)(16 * lane + 512 * i)));
            x[4 * i] = f.x; x[4 * i + 1] = f.y; x[4 * i + 2] = f.z; x[4 * i + 3] = f.w;
            mx = fmaxf(mx, fmaxf(fmaxf(f.x, f.y), fmaxf(f.z, f.w)));
        }
        #pragma unroll
        for (int o = 16; o > 0; o >>= 1)
            mx = fmaxf(mx, __shfl_xor_sync(0xFFFFFFFF, mx, o));
        float s = 0.0f;
        #pragma unroll
        for (int i = 0; i < 32; i++) { x[i] = __expf(x[i] - mx); s += x[i]; }
        #pragma unroll
        for (int o = 16; o > 0; o >>= 1)
            s += __shfl_xor_sync(0xFFFFFFFF, s, o);
        float inv = 1.0f / s;
        float* wrow = weights + ((size_t)bh * 1024 + q0 + r) * 1024;
        #pragma unroll
        for (int i = 0; i < 8; i++) {
            float p0 = x[4 * i] * inv, p1 = x[4 * i + 1] * inv;
            float p2 = x[4 * i + 2] * inv, p3 = x[4 * i + 3] * inv;
            STG_CS_F4(wrow + 4 * lane + 128 * i, p0, p1, p2, p3);
            uint32_t jb = (uint32_t)(4 * lane + 128 * i) * 2;
            *(uint2*)(smem + PADDR(r, jb)) = make_uint2(pack_hi(p0, p1), pack_hi(p2, p3));
        }
    }
    __syncthreads();

    // ---- AV: 8 chunks of 128 s; 1-pass Ph*Vh; warps = 2m x 2kh x 4d ----
    // Even/odd ks accumulators for 2x chain ILP; merged at the end.
    const int wm2 = wid >> 3;
    const int kh2 = (wid >> 2) & 1;
    const int nt_w = wid & 3;
    const int tb_row = (lane & 7) + ((lane >> 3) & 1) * 8;
    const int tb_cb = ((lane >> 4) & 1) * 16;
    float cav[2][2][4];   // [parity][nt][4]
    #pragma unroll
    for (int pp = 0; pp < 2; pp++)
        #pragma unroll
        for (int j = 0; j < 2; j++)
            #pragma unroll
            for (int u = 0; u < 4; u++) cav[pp][j][u] = 0.0f;

    #pragma unroll 1
    for (int sc = 0; sc < 8; sc++) {
        const int s0 = sc * 128;
        if (sc < 6)      { CP_WAIT(2); }
        else if (sc == 6){ CP_WAIT(1); }
        else             { CP_WAIT(0); }
        __syncthreads();
        if (sc + 3 < 8) fill_chunk((sc + 3) & 3, 2, s0 + 384);
        const uint32_t vbuf = KB(sc & 3);

        #pragma unroll
        for (int ks = 0; ks < 4; ks++) {
            int kl = kh2 * 64 + ks * 16;
            uint32_t fp[4], fvh[4];
            uint32_t prow = wm2 * 16 + (lane & 15);
            uint32_t jb = (uint32_t)(s0 + kl) * 2 + a_cb;
            ldsm4(fp, sb + PADDR(prow, jb));
            uint32_t offB = SWZ((uint32_t)((kl + tb_row) * 128 + nt_w * 32 + tb_cb));
            ldsm4t(fvh, sb + vbuf + offB);
            hmma(cav[ks & 1][0], fp, &fvh[0]);
            hmma(cav[ks & 1][1], fp, &fvh[2]);
        }
    }
    __syncthreads();

    // merge parities, reduce kh=1 into kh=0, then epilogue
    float cfin[2][4];
    #pragma unroll
    for (int j = 0; j < 2; j++)
        #pragma unroll
        for (int u = 0; u < 4; u++) cfin[j][u] = cav[0][j][u] + cav[1][j][u];

    if (kh2 == 1) {
        #pragma unroll
        for (int f = 0; f < 2; f++)
            *(float4*)(smem + OFF_RED + (((wm2 * 4 + nt_w) * 2 + f) * 32 + lane) * 16) =
                make_float4(cfin[f][0], cfin[f][1], cfin[f][2], cfin[f][3]);
    }
    __syncthreads();
    if (kh2 == 0) {
        #pragma unroll
        for (int f = 0; f < 2; f++) {
            float4 r4 = *(float4*)(smem + OFF_RED + (((wm2 * 4 + nt_w) * 2 + f) * 32 + lane) * 16);
            cfin[f][0] += r4.x; cfin[f][1] += r4.y; cfin[f][2] += r4.z; cfin[f][3] += r4.w;
            int srow = q0 + wm2 * 16 + (lane >> 2);
            int d = nt_w * 16 + f * 8 + 2 * (lane & 3);
            size_t i0 = ((size_t)(b * 1024 + srow)) * 1024 + h * 64 + d;
            size_t i1 = i0 + (size_t)8 * 1024;
            *(uint32_t*)(AOH + i0) = pack_hi(cfin[f][0], cfin[f][1]);
            *(uint32_t*)(AOL + i0) = pack_lo(cfin[f][0], cfin[f][1]);
            *(uint32_t*)(AOH + i1) = pack_hi(cfin[f][2], cfin[f][3]);
            *(uint32_t*)(AOL + i1) = pack_lo(cfin[f][2], cfin[f][3]);
        }
    }
}

// ================= launch =================
extern "C" void kernel_launch(void* const* d_in, const int* in_sizes, int n_in,
                              void* d_out, int out_size)
{
    const float* hs   = (const float*)d_in[0];
    const int*   mask = (const int*)  d_in[1];
    const float* Wq   = (const float*)d_in[2];
    const float* Wk   = (const float*)d_in[3];
    const float* Wv   = (const float*)d_in[4];
    const float* Wo   = (const float*)d_in[5];
    const float* rb   = (const float*)d_in[6];
    float* out = (float*)d_out;
    float* weights = out + (size_t)BATCH * S_LEN * DMODEL;

    half *hsH, *hsL, *WH, *WL, *QKVH, *QKVL, *AOH, *AOL;
    cudaGetSymbolAddress((void**)&hsH,  g_hsH);
    cudaGetSymbolAddress((void**)&hsL,  g_hsL);
    cudaGetSymbolAddress((void**)&WH,   g_WH);
    cudaGetSymbolAddress((void**)&WL,   g_WL);
    cudaGetSymbolAddress((void**)&QKVH, g_QKVH);
    cudaGetSymbolAddress((void**)&QKVL, g_QKVL);
    cudaGetSymbolAddress((void**)&AOH,  g_AOH);
    cudaGetSymbolAddress((void**)&AOL,  g_AOL);

    cudaFuncSetAttribute(proj_gemm<0>, cudaFuncAttributeMaxDynamicSharedMemorySize, PSMEM);
    cudaFuncSetAttribute(proj_gemm<1>, cudaFuncAttributeMaxDynamicSharedMemorySize, PSMEM);
    cudaFuncSetAttribute(attn_fused, cudaFuncAttributeMaxDynamicSharedMemorySize, ASMEM);

    bias_kernel<<<8, 256>>>(rb);
    split_all_kernel<<<dim3(4096, 1, 5), 256>>>(hs, Wq, Wk, Wv, Wo, hsH, hsL, WH, WL);

    // Q/K/V projections (z selects weight + dst slice; Q 3-pass, K/V 2-pass)
    proj_gemm<1><<<dim3(8, 32, 3), 512, PSMEM>>>(hsH, hsL, WH, WL, nullptr, QKVH, QKVL);

    // fused scores + bias + mask + softmax + weights + AV
    attn_fused<<<dim3(32, 64), 512, ASMEM>>>(mask, weights, QKVH, QKVL, AOH, AOL);

    // output projection (2-pass, Wo hi only)
    proj_gemm<0><<<dim3(8, 32, 1), 512, PSMEM>>>(
        AOH, AOL, WH + 3145728, WL + 3145728, out, nullptr, nullptr);
}